// round 6
// baseline (speedup 1.0000x reference)
#include <cuda_runtime.h>
#include <cstdint>
#include <math.h>

// ---------------------------------------------------------------------------
// MultiHeadAttention: B=8, S=1024, D=1024, H=16, HD=64
// Round 5: pre-rounded (tf32) + pre-k-permuted operands everywhere -> all
// fragment loads are single LDS.64 with no cvt in inner loops.
// GEMM: 256x128x32 tiles, 3-buffer cp.async ring. Attention: 2 CTAs/SM.
// ---------------------------------------------------------------------------

#define B_  8
#define S_  1024
#define D_  1024
#define H_  16
#define HD_ 64
#define M_TOTAL (B_ * S_)          // 8192

__device__ float g_q[(size_t)M_TOTAL * D_];
__device__ float g_k[(size_t)M_TOTAL * D_];
__device__ float g_v[(size_t)M_TOTAL * D_];
__device__ float g_c[(size_t)M_TOTAL * D_];
__device__ float g_xt[(size_t)M_TOTAL * D_];   // x  tf32-rounded, k-permuted
__device__ float g_wq[(size_t)D_ * D_];
__device__ float g_wk[(size_t)D_ * D_];
__device__ float g_wv[(size_t)D_ * D_];
__device__ float g_wo[(size_t)D_ * D_];

// ---------------------------------------------------------------------------
// helpers
// ---------------------------------------------------------------------------
__device__ __forceinline__ unsigned f2tf32(float f) {
    unsigned u;
    asm("cvt.rna.tf32.f32 %0, %1;" : "=r"(u) : "f"(f));
    return u;
}
__device__ __forceinline__ float tf32f(float f) { return __uint_as_float(f2tf32(f)); }

__device__ __forceinline__ uint32_t smem_u32(const void* p) {
    uint32_t a;
    asm("{ .reg .u64 t; cvta.to.shared.u64 t, %1; cvt.u32.u64 %0, t; }"
        : "=r"(a) : "l"(p));
    return a;
}

__device__ __forceinline__ void cpa16(uint32_t dst, const float* src) {
    asm volatile("cp.async.cg.shared.global [%0], [%1], 16;"
                 :: "r"(dst), "l"(src) : "memory");
}
__device__ __forceinline__ void cpa_commit() {
    asm volatile("cp.async.commit_group;" ::: "memory");
}
__device__ __forceinline__ void cpa_wait1() {
    asm volatile("cp.async.wait_group 1;" ::: "memory");
}
__device__ __forceinline__ void cpa_wait0() {
    asm volatile("cp.async.wait_group 0;" ::: "memory");
}

__device__ __forceinline__ void mma_tf32(float* c,
                                         unsigned a0, unsigned a1, unsigned a2, unsigned a3,
                                         unsigned b0, unsigned b1) {
    asm volatile(
        "mma.sync.aligned.m16n8k8.row.col.f32.tf32.tf32.f32 "
        "{%0,%1,%2,%3}, {%4,%5,%6,%7}, {%8,%9}, {%0,%1,%2,%3};\n"
        : "+f"(c[0]), "+f"(c[1]), "+f"(c[2]), "+f"(c[3])
        : "r"(a0), "r"(a1), "r"(a2), "r"(a3), "r"(b0), "r"(b1));
}

// ---------------------------------------------------------------------------
// Pre-pass: dst[row][pos(k)] = tf32(src[row][k]) for 1024-wide rows, where
// pos permutes each aligned 8-group into fragment order [0,4,1,5,2,6,3,7]:
// pos(k) = ((k&3)<<1) | (k>>2). One float4 per thread (k group offset 0 or 4).
// ---------------------------------------------------------------------------
__global__ __launch_bounds__(256)
void prep_tf32(const float* __restrict__ src, float* __restrict__ dst, int n4)
{
    const int i = blockIdx.x * blockDim.x + threadIdx.x;
    if (i >= n4) return;
    const float4 v = ((const float4*)src)[i];
    const int k    = i << 2;
    const int row  = k >> 10;
    const int kk   = k & 1023;
    float* d = dst + ((size_t)row << 10) + (kk & ~7) + ((kk & 4) ? 1 : 0);
    d[0] = tf32f(v.x);
    d[2] = tf32f(v.y);
    d[4] = tf32f(v.z);
    d[6] = tf32f(v.w);
}

// ---------------------------------------------------------------------------
// tf32 GEMM (NT): C_z[m][n] = (sum_k A[m][k]*W_z[n][k] + bias_z[n]) * scale_z
// A, W pre-rounded + k-permuted. CTA 256x128, BK=32, 8 warps of 64x64.
// 3-buffer cp.async ring, issue-before-compute. GLD=40 (≡8 mod 32):
// fragment LDS.64 strictly conflict-free.
// permOut: epilogue writes tf32-rounded values at k-permuted columns.
// ---------------------------------------------------------------------------
#define GBM 256
#define GBN 128
#define GBK 32
#define GLD 40
#define GBUF ((GBM + GBN) * GLD)                 // floats per stage
#define GEMM_SMEM (3 * GBUF * 4)                 // 184320 bytes

__global__ __launch_bounds__(256, 1)
void gemm_tc(const float* __restrict__ A,
             const float* __restrict__ W0, const float* __restrict__ W1,
             const float* __restrict__ W2,
             const float* __restrict__ bb0, const float* __restrict__ bb1,
             const float* __restrict__ bb2,
             float* __restrict__ C0, float* __restrict__ C1, float* __restrict__ C2,
             float scale0, int permOut)
{
    extern __shared__ float smem[];
    const int z = blockIdx.z;
    const float* Bw   = (z == 0) ? W0  : (z == 1) ? W1  : W2;
    const float* bias = (z == 0) ? bb0 : (z == 1) ? bb1 : bb2;
    float*       C    = (z == 0) ? C0  : (z == 1) ? C1  : C2;
    const float scale = (z == 0) ? scale0 : 1.0f;

    const int tid  = threadIdx.x;
    const int wid  = tid >> 5;
    const int lane = tid & 31;
    const int g    = lane >> 2;
    const int tig  = lane & 3;
    const int wm   = (wid & 3) * 64;
    const int wn   = (wid >> 2) * 64;
    const int bm   = blockIdx.y * GBM;
    const int bn   = blockIdx.x * GBN;

    const float* Abase = A  + (size_t)bm * D_;
    const float* Bbase = Bw + (size_t)bn * D_;
    const uint32_t su  = smem_u32(smem);

#define G_ISSUE(slab) do {                                                 \
        const uint32_t s0 = su + (uint32_t)((slab) % 3) * (GBUF * 4);      \
        const int k0 = (slab) * GBK;                                       \
        _Pragma("unroll")                                                  \
        for (int j = 0; j < 8; j++) {                                      \
            const int i = tid + 256 * j;                                   \
            const int row = i >> 3, ch = (i & 7) * 4;                      \
            cpa16(s0 + (row * GLD + ch) * 4,                               \
                  Abase + (size_t)row * D_ + k0 + ch);                     \
        }                                                                  \
        _Pragma("unroll")                                                  \
        for (int j = 0; j < 4; j++) {                                      \
            const int i = tid + 256 * j;                                   \
            const int row = i >> 3, ch = (i & 7) * 4;                      \
            cpa16(s0 + ((GBM + row) * GLD + ch) * 4,                       \
                  Bbase + (size_t)row * D_ + k0 + ch);                     \
        }                                                                  \
        cpa_commit();                                                      \
    } while (0)

    float acc[4][8][4];
#pragma unroll
    for (int mt = 0; mt < 4; mt++)
#pragma unroll
        for (int nt = 0; nt < 8; nt++)
#pragma unroll
            for (int i = 0; i < 4; i++) acc[mt][nt][i] = 0.f;

    const int NT = D_ / GBK;   // 32
    G_ISSUE(0);
    G_ISSUE(1);

    for (int t = 0; t < NT; t++) {
        if (t == NT - 1) cpa_wait0(); else cpa_wait1();
        __syncthreads();
        if (t + 2 < NT) G_ISSUE(t + 2);   // writes buf (t+2)%3 != t%3, (t+1)%3

        const float* as = smem + (t % 3) * GBUF;
        const float* bs = as + GBM * GLD;
#pragma unroll
        for (int ks = 0; ks < 4; ks++) {
            unsigned af[4][4];
#pragma unroll
            for (int mt = 0; mt < 4; mt++) {
                const int qr = (wm + mt * 16 + g) * GLD + ks * 8 + 2 * tig;
                const float2 lo = *(const float2*)&as[qr];
                const float2 hi = *(const float2*)&as[qr + 8 * GLD];
                af[mt][0] = __float_as_uint(lo.x);
                af[mt][1] = __float_as_uint(hi.x);
                af[mt][2] = __float_as_uint(lo.y);
                af[mt][3] = __float_as_uint(hi.y);
            }
#pragma unroll
            for (int nt = 0; nt < 8; nt++) {
                const int kr = (wn + nt * 8 + g) * GLD + ks * 8 + 2 * tig;
                const float2 bb = *(const float2*)&bs[kr];
                const unsigned b0 = __float_as_uint(bb.x);
                const unsigned b1 = __float_as_uint(bb.y);
#pragma unroll
                for (int mt = 0; mt < 4; mt++)
                    mma_tf32(acc[mt][nt], af[mt][0], af[mt][1], af[mt][2], af[mt][3],
                             b0, b1);
            }
        }
    }
#undef G_ISSUE

    // epilogue
    if (permOut) {
        const int pp = ((tig & 1) << 2) | (tig >> 1);   // pos(2*tig)
#pragma unroll
        for (int mt = 0; mt < 4; mt++) {
            const int row0 = bm + wm + mt * 16 + g;
#pragma unroll
            for (int nt = 0; nt < 8; nt++) {
                const int cb = bn + wn + nt * 8;
                const float c0 = bias[cb + 2 * tig], c1 = bias[cb + 2 * tig + 1];
                float* d0 = C + (size_t)row0 * D_ + cb;
                float* d1 = C + (size_t)(row0 + 8) * D_ + cb;
                d0[pp]     = tf32f((acc[mt][nt][0] + c0) * scale);
                d0[pp + 2] = tf32f((acc[mt][nt][1] + c1) * scale);
                d1[pp]     = tf32f((acc[mt][nt][2] + c0) * scale);
                d1[pp + 2] = tf32f((acc[mt][nt][3] + c1) * scale);
            }
        }
    } else {
#pragma unroll
        for (int mt = 0; mt < 4; mt++) {
            const int row0 = bm + wm + mt * 16 + g;
#pragma unroll
            for (int nt = 0; nt < 8; nt++) {
                const int col = bn + wn + nt * 8 + 2 * tig;
                const float c0 = bias[col], c1 = bias[col + 1];
                float2 v0 = make_float2(acc[mt][nt][0] + c0, acc[mt][nt][1] + c1);
                float2 v1 = make_float2(acc[mt][nt][2] + c0, acc[mt][nt][3] + c1);
                *(float2*)(C + (size_t)row0 * D_ + col)       = v0;
                *(float2*)(C + (size_t)(row0 + 8) * D_ + col) = v1;
            }
        }
    }
}

// ---------------------------------------------------------------------------
// Flash attention, tf32 mma.sync, cp.async double-buffered K/V, 2 CTAs/SM.
// Q/K/V pre-rounded; Q/K pre-permuted in head-dim -> LDS.64 frags, no cvt.
// V column labels permuted -> O inherits them, matching Wo's k-permutation.
// Pads = 72 (≡8 mod 32): all fragment accesses strictly conflict-free.
// ---------------------------------------------------------------------------
#define QLD 72
#define KLD 72
#define VLD 72
#define OFF_K(buf) (128 * QLD + (buf) * 64 * KLD)
#define OFF_V(buf) (128 * QLD + 2 * 64 * KLD + (buf) * 64 * VLD)
#define ATTN_SMEM ((128 * QLD + 2 * 64 * KLD + 2 * 64 * VLD) * 4)   // 110592 B

__device__ __forceinline__ void p2afrag(const float sv[4], int lane, int tig,
                                        unsigned& a0, unsigned& a1,
                                        unsigned& a2, unsigned& a3) {
    const unsigned F = 0xffffffffu;
    const int s0l = (lane & ~3) | (tig >> 1);
    const int s1l = s0l + 2;
    float v00 = __shfl_sync(F, sv[0], s0l);
    float v01 = __shfl_sync(F, sv[1], s0l);
    float v10 = __shfl_sync(F, sv[0], s1l);
    float v11 = __shfl_sync(F, sv[1], s1l);
    float w00 = __shfl_sync(F, sv[2], s0l);
    float w01 = __shfl_sync(F, sv[3], s0l);
    float w10 = __shfl_sync(F, sv[2], s1l);
    float w11 = __shfl_sync(F, sv[3], s1l);
    const bool odd = (tig & 1);
    a0 = f2tf32(odd ? v01 : v00);
    a2 = f2tf32(odd ? v11 : v10);
    a1 = f2tf32(odd ? w01 : w00);
    a3 = f2tf32(odd ? w11 : w10);
}

__global__ __launch_bounds__(128, 2)
void attn_tc(const float* __restrict__ Q, const float* __restrict__ K,
             const float* __restrict__ V, float* __restrict__ O)
{
    extern __shared__ float sm[];
    const uint32_t su = smem_u32(sm);

    const int q0   = blockIdx.x * 128;
    const int h    = blockIdx.y;
    const int b    = blockIdx.z;
    const int tid  = threadIdx.x;
    const int w    = tid >> 5;
    const int lane = tid & 31;
    const int g    = lane >> 2;
    const int tig  = lane & 3;

    const size_t base = (size_t)b * S_ * D_ + (size_t)h * HD_;

#define A_ISSUE(t, buf) do {                                               \
        const float* Kb = K + base + (size_t)((t) * 64) * D_;              \
        const float* Vb = V + base + (size_t)((t) * 64) * D_;              \
        _Pragma("unroll")                                                  \
        for (int j = 0; j < 8; j++) {                                      \
            const int i = tid + 128 * j;                                   \
            const int row = i >> 4, c4 = (i & 15) * 4;                     \
            cpa16(su + (OFF_K(buf) + row * KLD + c4) * 4,                  \
                  Kb + (size_t)row * D_ + c4);                             \
            cpa16(su + (OFF_V(buf) + row * VLD + c4) * 4,                  \
                  Vb + (size_t)row * D_ + c4);                             \
        }                                                                  \
        cpa_commit();                                                      \
    } while (0)

    {
        const float* Qb = Q + base + (size_t)q0 * D_;
        const float* Kb = K + base;
        const float* Vb = V + base;
#pragma unroll
        for (int j = 0; j < 16; j++) {
            const int i = tid + 128 * j;
            const int row = i >> 4, c4 = (i & 15) * 4;
            cpa16(su + (row * QLD + c4) * 4, Qb + (size_t)row * D_ + c4);
        }
#pragma unroll
        for (int j = 0; j < 8; j++) {
            const int i = tid + 128 * j;
            const int row = i >> 4, c4 = (i & 15) * 4;
            cpa16(su + (OFF_K(0) + row * KLD + c4) * 4, Kb + (size_t)row * D_ + c4);
            cpa16(su + (OFF_V(0) + row * VLD + c4) * 4, Vb + (size_t)row * D_ + c4);
        }
        cpa_commit();
        A_ISSUE(1, 1);
    }

    float mrow[2][2], lrow[2][2];
#pragma unroll
    for (int mt = 0; mt < 2; mt++) {
        mrow[mt][0] = -1e30f; mrow[mt][1] = -1e30f;
        lrow[mt][0] = 0.f;    lrow[mt][1] = 0.f;
    }
    float o[2][8][4];
#pragma unroll
    for (int mt = 0; mt < 2; mt++)
#pragma unroll
        for (int nt = 0; nt < 8; nt++)
#pragma unroll
            for (int i = 0; i < 4; i++) o[mt][nt][i] = 0.f;

    const int NTILE = S_ / 64;   // 16
    for (int t = 0; t < NTILE; t++) {
        if (t == NTILE - 1) cpa_wait0(); else cpa_wait1();
        __syncthreads();

        const float* sQ = sm;
        const float* sK = sm + OFF_K(t & 1);
        const float* sV = sm + OFF_V(t & 1);

        // ---- S = Q . K^T ----
        float s[2][8][4];
#pragma unroll
        for (int mt = 0; mt < 2; mt++)
#pragma unroll
            for (int nt = 0; nt < 8; nt++)
#pragma unroll
                for (int i = 0; i < 4; i++) s[mt][nt][i] = 0.f;

#pragma unroll
        for (int ks = 0; ks < 8; ks++) {
            unsigned af[2][4];
#pragma unroll
            for (int mt = 0; mt < 2; mt++) {
                const int qr = (w * 32 + mt * 16 + g) * QLD + ks * 8 + 2 * tig;
                const float2 lo = *(const float2*)&sQ[qr];
                const float2 hi = *(const float2*)&sQ[qr + 8 * QLD];
                af[mt][0] = __float_as_uint(lo.x);
                af[mt][1] = __float_as_uint(hi.x);
                af[mt][2] = __float_as_uint(lo.y);
                af[mt][3] = __float_as_uint(hi.y);
            }
#pragma unroll
            for (int nt = 0; nt < 8; nt++) {
                const int kr = (nt * 8 + g) * KLD + ks * 8 + 2 * tig;
                const float2 bb = *(const float2*)&sK[kr];
                const unsigned b0 = __float_as_uint(bb.x);
                const unsigned b1 = __float_as_uint(bb.y);
                mma_tf32(s[0][nt], af[0][0], af[0][1], af[0][2], af[0][3], b0, b1);
                mma_tf32(s[1][nt], af[1][0], af[1][1], af[1][2], af[1][3], b0, b1);
            }
        }

        // ---- online softmax ----
#pragma unroll
        for (int mt = 0; mt < 2; mt++) {
            float mx0 = -1e30f, mx1 = -1e30f;
#pragma unroll
            for (int nt = 0; nt < 8; nt++) {
                mx0 = fmaxf(mx0, fmaxf(s[mt][nt][0], s[mt][nt][1]));
                mx1 = fmaxf(mx1, fmaxf(s[mt][nt][2], s[mt][nt][3]));
            }
            mx0 = fmaxf(mx0, __shfl_xor_sync(0xffffffffu, mx0, 1));
            mx0 = fmaxf(mx0, __shfl_xor_sync(0xffffffffu, mx0, 2));
            mx1 = fmaxf(mx1, __shfl_xor_sync(0xffffffffu, mx1, 1));
            mx1 = fmaxf(mx1, __shfl_xor_sync(0xffffffffu, mx1, 2));

            const float nm0 = fmaxf(mrow[mt][0], mx0);
            const float nm1 = fmaxf(mrow[mt][1], mx1);
            const float al0 = __expf(mrow[mt][0] - nm0);
            const float al1 = __expf(mrow[mt][1] - nm1);
            mrow[mt][0] = nm0; mrow[mt][1] = nm1;

            float ps0 = 0.f, ps1 = 0.f;
#pragma unroll
            for (int nt = 0; nt < 8; nt++) {
                s[mt][nt][0] = __expf(s[mt][nt][0] - nm0);
                s[mt][nt][1] = __expf(s[mt][nt][1] - nm0);
                s[mt][nt][2] = __expf(s[mt][nt][2] - nm1);
                s[mt][nt][3] = __expf(s[mt][nt][3] - nm1);
                ps0 += s[mt][nt][0] + s[mt][nt][1];
                ps1 += s[mt][nt][2] + s[mt][nt][3];
            }
            ps0 += __shfl_xor_sync(0xffffffffu, ps0, 1);
            ps0 += __shfl_xor_sync(0xffffffffu, ps0, 2);
            ps1 += __shfl_xor_sync(0xffffffffu, ps1, 1);
            ps1 += __shfl_xor_sync(0xffffffffu, ps1, 2);
            lrow[mt][0] = lrow[mt][0] * al0 + ps0;
            lrow[mt][1] = lrow[mt][1] * al1 + ps1;

#pragma unroll
            for (int nt = 0; nt < 8; nt++) {
                o[mt][nt][0] *= al0; o[mt][nt][1] *= al0;
                o[mt][nt][2] *= al1; o[mt][nt][3] *= al1;
            }
        }

        // ---- O += P . V ----
#pragma unroll
        for (int ks = 0; ks < 8; ks++) {
            unsigned pa[2][4];
            p2afrag(s[0][ks], lane, tig, pa[0][0], pa[0][1], pa[0][2], pa[0][3]);
            p2afrag(s[1][ks], lane, tig, pa[1][0], pa[1][1], pa[1][2], pa[1][3]);
#pragma unroll
            for (int nt = 0; nt < 8; nt++) {
                const int vr = (ks * 8 + tig) * VLD + nt * 8 + g;
                const unsigned b0 = __float_as_uint(sV[vr]);
                const unsigned b1 = __float_as_uint(sV[vr + 4 * VLD]);
                mma_tf32(o[0][nt], pa[0][0], pa[0][1], pa[0][2], pa[0][3], b0, b1);
                mma_tf32(o[1][nt], pa[1][0], pa[1][1], pa[1][2], pa[1][3], b0, b1);
            }
        }

        __syncthreads();
        if (t + 2 < NTILE) A_ISSUE(t + 2, t & 1);
    }
#undef A_ISSUE

    // ---- write out (tf32-rounded for the O-proj consumer) ----
#pragma unroll
    for (int mt = 0; mt < 2; mt++) {
        const float inv0 = 1.f / lrow[mt][0];
        const float inv1 = 1.f / lrow[mt][1];
        const int row = q0 + w * 32 + mt * 16 + g;
#pragma unroll
        for (int nt = 0; nt < 8; nt++) {
            const int col = nt * 8 + 2 * tig;
            float2 v0 = make_float2(tf32f(o[mt][nt][0] * inv0), tf32f(o[mt][nt][1] * inv0));
            float2 v1 = make_float2(tf32f(o[mt][nt][2] * inv1), tf32f(o[mt][nt][3] * inv1));
            *(float2*)(O + base + (size_t)row * D_ + col)       = v0;
            *(float2*)(O + base + (size_t)(row + 8) * D_ + col) = v1;
        }
    }
}

// ---------------------------------------------------------------------------
// Launch
// ---------------------------------------------------------------------------
extern "C" void kernel_launch(void* const* d_in, const int* in_sizes, int n_in,
                              void* d_out, int out_size)
{
    const float* x  = (const float*)d_in[0];
    const float* Wq = (const float*)d_in[1];
    const float* Wk = (const float*)d_in[2];
    const float* Wv = (const float*)d_in[3];
    const float* bq = (const float*)d_in[4];
    const float* bk = (const float*)d_in[5];
    const float* bv = (const float*)d_in[6];
    const float* Wo = (const float*)d_in[7];
    const float* bo = (const float*)d_in[8];
    float* out = (float*)d_out;

    float *qp, *kp, *vp, *cp, *xt, *wq, *wk, *wv, *wo;
    cudaGetSymbolAddress((void**)&qp, g_q);
    cudaGetSymbolAddress((void**)&kp, g_k);
    cudaGetSymbolAddress((void**)&vp, g_v);
    cudaGetSymbolAddress((void**)&cp, g_c);
    cudaGetSymbolAddress((void**)&xt, g_xt);
    cudaGetSymbolAddress((void**)&wq, g_wq);
    cudaGetSymbolAddress((void**)&wk, g_wk);
    cudaGetSymbolAddress((void**)&wv, g_wv);
    cudaGetSymbolAddress((void**)&wo, g_wo);

    cudaFuncSetAttribute(gemm_tc,
                         cudaFuncAttributeMaxDynamicSharedMemorySize, GEMM_SMEM);
    cudaFuncSetAttribute(attn_tc,
                         cudaFuncAttributeMaxDynamicSharedMemorySize, ATTN_SMEM);

    // pre-pass: tf32 round + k-permute
    const int n4x = M_TOTAL * D_ / 4;          // 2097152
    const int n4w = D_ * D_ / 4;               // 262144
    prep_tf32<<<(n4x + 255) / 256, 256>>>(x,  xt, n4x);
    prep_tf32<<<(n4w + 255) / 256, 256>>>(Wq, wq, n4w);
    prep_tf32<<<(n4w + 255) / 256, 256>>>(Wk, wk, n4w);
    prep_tf32<<<(n4w + 255) / 256, 256>>>(Wv, wv, n4w);
    prep_tf32<<<(n4w + 255) / 256, 256>>>(Wo, wo, n4w);

    // fused QKV (permuted + rounded outputs feed attention)
    gemm_tc<<<dim3(D_ / GBN, M_TOTAL / GBM, 3), 256, GEMM_SMEM>>>(
        xt, wq, wk, wv, bq, bk, bv, qp, kp, vp, 0.125f, 1);

    attn_tc<<<dim3(S_ / 128, H_, B_), 128, ATTN_SMEM>>>(qp, kp, vp, cp);

    // output projection (true layout, full fp32 out)
    gemm_tc<<<dim3(D_ / GBN, M_TOTAL / GBM, 1), 256, GEMM_SMEM>>>(
        cp, wo, wo, wo, bo, bo, bo, out, out, out, 1.0f, 0);
}

// round 7
// speedup vs baseline: 1.6894x; 1.6894x over previous
#include <cuda_runtime.h>
#include <cuda_fp16.h>
#include <cstdint>
#include <math.h>

// ---------------------------------------------------------------------------
// MultiHeadAttention: B=8, S=1024, D=1024, H=16, HD=64
// Round 6: fp16 m16n8k16 mma everywhere (fp32 accum). Pre-converted fp16
// operands with unit-permutation (k,k+8 adjacent) -> LDS.64 fragments.
// V pre-transposed by GEMM epilogue -> PV B-frags are direct LDS.32.
// S->P fragment conversion is register-local (no shuffles).
// ---------------------------------------------------------------------------

#define B_  8
#define S_  1024
#define D_  1024
#define H_  16
#define HD_ 64
#define M_TOTAL (B_ * S_)          // 8192

__device__ __half g_xh[(size_t)M_TOTAL * D_];
__device__ __half g_qh[(size_t)M_TOTAL * D_];
__device__ __half g_kh[(size_t)M_TOTAL * D_];
__device__ __half g_vt[(size_t)B_ * H_ * HD_ * S_];   // [B][H][d][key]
__device__ __half g_ch[(size_t)M_TOTAL * D_];
__device__ __half g_wq[(size_t)D_ * D_];
__device__ __half g_wk[(size_t)D_ * D_];
__device__ __half g_wv[(size_t)D_ * D_];
__device__ __half g_wo[(size_t)D_ * D_];

// ---------------------------------------------------------------------------
// helpers
// ---------------------------------------------------------------------------
__device__ __forceinline__ uint32_t smem_u32(const void* p) {
    uint32_t a;
    asm("{ .reg .u64 t; cvta.to.shared.u64 t, %1; cvt.u32.u64 %0, t; }"
        : "=r"(a) : "l"(p));
    return a;
}

__device__ __forceinline__ void cpa16(uint32_t dst, const void* src) {
    asm volatile("cp.async.cg.shared.global [%0], [%1], 16;"
                 :: "r"(dst), "l"(src) : "memory");
}
__device__ __forceinline__ void cpa_commit() {
    asm volatile("cp.async.commit_group;" ::: "memory");
}
__device__ __forceinline__ void cpa_wait1() {
    asm volatile("cp.async.wait_group 1;" ::: "memory");
}
__device__ __forceinline__ void cpa_wait0() {
    asm volatile("cp.async.wait_group 0;" ::: "memory");
}

__device__ __forceinline__ void mma_f16(float* c,
                                        uint32_t a0, uint32_t a1, uint32_t a2, uint32_t a3,
                                        uint32_t b0, uint32_t b1) {
    asm volatile(
        "mma.sync.aligned.m16n8k16.row.col.f32.f16.f16.f32 "
        "{%0,%1,%2,%3}, {%4,%5,%6,%7}, {%8,%9}, {%0,%1,%2,%3};\n"
        : "+f"(c[0]), "+f"(c[1]), "+f"(c[2]), "+f"(c[3])
        : "r"(a0), "r"(a1), "r"(a2), "r"(a3), "r"(b0), "r"(b1));
}

__device__ __forceinline__ uint32_t pack2(float lo, float hi) {
    __half2 h = __floats2half2_rn(lo, hi);
    return *reinterpret_cast<uint32_t*>(&h);
}

// ---------------------------------------------------------------------------
// Pre-pass: fp16 convert + unit-permute each aligned 16-k group so half2
// units (u, u+4) become adjacent: pos2(u) = ((u&3)<<1)|(u>>2).
// ---------------------------------------------------------------------------
__global__ __launch_bounds__(256)
void prep_h(const float* __restrict__ src, __half* __restrict__ dst, int n4)
{
    const int i = blockIdx.x * blockDim.x + threadIdx.x;
    if (i >= n4) return;
    const float4 v = ((const float4*)src)[i];
    const int flat = i << 2;
    const int base = flat & ~15;
    const int u0   = (flat & 15) >> 1;           // 0,2,4,6
    const int p0   = ((u0 & 3) << 1) | (u0 >> 2);
    const int u1   = u0 + 1;
    const int p1   = ((u1 & 3) << 1) | (u1 >> 2);
    *(__half2*)(dst + base + 2 * p0) = __floats2half2_rn(v.x, v.y);
    *(__half2*)(dst + base + 2 * p1) = __floats2half2_rn(v.z, v.w);
}

// ---------------------------------------------------------------------------
// fp16 GEMM (NT): C_z[m][n] = (sum_k A[m][k]*W_z[n][k] + bias_z[n]) * scale
// A,W fp16 unit-permuted. CTA 256x128, k-slab 32, 8 warps of 64x64,
// 3-buffer cp.async ring. Row stride 80 halves (160B: word-stride 8 mod 32,
// frag LDS.64 conflict-free per 16-lane phase).
// Epilogues: z<2 -> fp16 unit-permuted (q/k); z==2 -> transposed Vt fp16;
// oproj -> plain fp32.
// ---------------------------------------------------------------------------
#define GBM 256
#define GBN 128
#define GBKH 32
#define GLDH 80
#define GBUFH ((GBM + GBN) * GLDH)               // 30720 halves / buffer
#define GEMM_SMEM (3 * GBUFH * 2)                // 184320 bytes

__global__ __launch_bounds__(256, 1)
void gemm_h(const __half* __restrict__ A,
            const __half* __restrict__ W0, const __half* __restrict__ W1,
            const __half* __restrict__ W2,
            const float* __restrict__ bb0, const float* __restrict__ bb1,
            const float* __restrict__ bb2,
            void* C0, void* C1, void* C2,
            int oproj)
{
    extern __shared__ __half smh[];
    const int z = blockIdx.z;
    const __half* Bw   = (z == 0) ? W0  : (z == 1) ? W1  : W2;
    const float*  bias = (z == 0) ? bb0 : (z == 1) ? bb1 : bb2;
    void*         C    = (z == 0) ? C0  : (z == 1) ? C1  : C2;
    const float scale  = (!oproj && z == 0) ? 0.125f : 1.0f;

    const int tid  = threadIdx.x;
    const int wid  = tid >> 5;
    const int lane = tid & 31;
    const int g    = lane >> 2;
    const int tig  = lane & 3;
    const int wm   = (wid & 3) * 64;
    const int wn   = (wid >> 2) * 64;
    const int bm   = blockIdx.y * GBM;
    const int bn   = blockIdx.x * GBN;

    const __half* Abase = A  + (size_t)bm * D_;
    const __half* Bbase = Bw + (size_t)bn * D_;
    const uint32_t su   = smem_u32(smh);

#define G_ISSUE(slab) do {                                                 \
        const uint32_t s0 = su + (uint32_t)((slab) % 3) * (GBUFH * 2);     \
        const int k0 = (slab) * GBKH;                                      \
        _Pragma("unroll")                                                  \
        for (int j = 0; j < 4; j++) {                                      \
            const int i = tid + 256 * j;        /* A: 1024 chunks */       \
            const int row = i >> 2, ch = (i & 3) * 8;                      \
            cpa16(s0 + (row * GLDH + ch) * 2,                              \
                  Abase + (size_t)row * D_ + k0 + ch);                     \
        }                                                                  \
        _Pragma("unroll")                                                  \
        for (int j = 0; j < 2; j++) {                                      \
            const int i = tid + 256 * j;        /* B: 512 chunks */        \
            const int row = i >> 2, ch = (i & 3) * 8;                      \
            cpa16(s0 + ((GBM + row) * GLDH + ch) * 2,                      \
                  Bbase + (size_t)row * D_ + k0 + ch);                     \
        }                                                                  \
        cpa_commit();                                                      \
    } while (0)

    float acc[4][8][4];
#pragma unroll
    for (int mt = 0; mt < 4; mt++)
#pragma unroll
        for (int nt = 0; nt < 8; nt++)
#pragma unroll
            for (int i = 0; i < 4; i++) acc[mt][nt][i] = 0.f;

    const int NT = D_ / GBKH;   // 32
    G_ISSUE(0);
    G_ISSUE(1);

    for (int t = 0; t < NT; t++) {
        if (t == NT - 1) cpa_wait0(); else cpa_wait1();
        __syncthreads();
        if (t + 2 < NT) G_ISSUE(t + 2);

        const __half* as = smh + (t % 3) * GBUFH;
        const __half* bs = as + GBM * GLDH;
#pragma unroll
        for (int ks = 0; ks < 2; ks++) {
            uint2 alo[4], ahi[4];
#pragma unroll
            for (int mt = 0; mt < 4; mt++) {
                const int r0 = (wm + mt * 16 + g) * GLDH + ks * 16 + 4 * tig;
                alo[mt] = *(const uint2*)&as[r0];             // a0, a2
                ahi[mt] = *(const uint2*)&as[r0 + 8 * GLDH];  // a1, a3
            }
#pragma unroll
            for (int nt = 0; nt < 8; nt++) {
                const uint2 bb = *(const uint2*)&bs[(wn + nt * 8 + g) * GLDH
                                                    + ks * 16 + 4 * tig];
#pragma unroll
                for (int mt = 0; mt < 4; mt++)
                    mma_f16(acc[mt][nt], alo[mt].x, ahi[mt].x, alo[mt].y, ahi[mt].y,
                            bb.x, bb.y);
            }
        }
    }
#undef G_ISSUE

    if (oproj) {
        // plain fp32 output
        float* Co = (float*)C;
#pragma unroll
        for (int mt = 0; mt < 4; mt++) {
            const int row0 = bm + wm + mt * 16 + g;
#pragma unroll
            for (int nt = 0; nt < 8; nt++) {
                const int col = bn + wn + nt * 8 + 2 * tig;
                const float c0 = bias[col], c1 = bias[col + 1];
                float2 v0 = make_float2(acc[mt][nt][0] + c0, acc[mt][nt][1] + c1);
                float2 v1 = make_float2(acc[mt][nt][2] + c0, acc[mt][nt][3] + c1);
                *(float2*)(Co + (size_t)row0 * D_ + col)       = v0;
                *(float2*)(Co + (size_t)(row0 + 8) * D_ + col) = v1;
            }
        }
    } else if (z < 2) {
        // fp16 unit-permuted output (q / k)
        __half* Ch = (__half*)C;
#pragma unroll
        for (int mt = 0; mt < 4; mt++) {
            const int row0 = bm + wm + mt * 16 + g;
#pragma unroll
            for (int nt = 0; nt < 8; nt++) {
                const int n = bn + wn + nt * 8 + 2 * tig;
                const int dsti = bn + wn + (nt & ~1) * 8 + 4 * tig + 2 * (nt & 1);
                const float c0 = bias[n], c1 = bias[n + 1];
                *(__half2*)(Ch + (size_t)row0 * D_ + dsti) =
                    __floats2half2_rn((acc[mt][nt][0] + c0) * scale,
                                      (acc[mt][nt][1] + c1) * scale);
                *(__half2*)(Ch + (size_t)(row0 + 8) * D_ + dsti) =
                    __floats2half2_rn((acc[mt][nt][2] + c0) * scale,
                                      (acc[mt][nt][3] + c1) * scale);
            }
        }
    } else {
        // transposed Vt output: Vt[b][h][dd][s]
        __half* Vt = (__half*)C;
#pragma unroll
        for (int mt = 0; mt < 4; mt++) {
            const int row0 = bm + wm + mt * 16 + g;
#pragma unroll
            for (int nt = 0; nt < 8; nt++) {
                const int n  = bn + wn + nt * 8 + 2 * tig;
                const float c0 = bias[n], c1 = bias[n + 1];
#pragma unroll
                for (int e = 0; e < 4; e++) {
                    const int row = row0 + (e >> 1) * 8;
                    const int col = n + (e & 1);
                    const float val = acc[mt][nt][e] + ((e & 1) ? c1 : c0);
                    const int bIdx = row >> 10, s = row & 1023;
                    const int head = col >> 6,  dd = col & 63;
                    Vt[(((size_t)(bIdx * H_ + head)) * HD_ + dd) * S_ + s] =
                        __float2half_rn(val);
                }
            }
        }
    }
}

// ---------------------------------------------------------------------------
// Flash attention, fp16 m16n8k16, cp.async double-buffered K/Vt, 2 CTAs/SM.
// Q/K fp16 unit-permuted (head-dim) -> LDS.64 frags. Vt [d][key] -> PV
// B-frags are 2x LDS.32. S C-frags pack register-locally into P A-frags.
// Strides: Q/K 80 halves (160B), Vt 72 halves (144B) -- conflict-free.
// ---------------------------------------------------------------------------
#define QLDH 80
#define KLDH 80
#define VLDH 72
#define OFF_Q 0
#define OFF_K(buf) (128 * QLDH + (buf) * 64 * KLDH)
#define OFF_V(buf) (128 * QLDH + 2 * 64 * KLDH + (buf) * 64 * VLDH)
#define ATTN_SMEM ((128 * QLDH + 2 * 64 * KLDH + 2 * 64 * VLDH) * 2)  // 59392 B

__global__ __launch_bounds__(128, 2)
void attn_h(const __half* __restrict__ Q, const __half* __restrict__ K,
            const __half* __restrict__ Vt, __half* __restrict__ O)
{
    extern __shared__ __half smh[];
    const uint32_t su = smem_u32(smh);

    const int q0   = blockIdx.x * 128;
    const int h    = blockIdx.y;
    const int b    = blockIdx.z;
    const int tid  = threadIdx.x;
    const int w    = tid >> 5;
    const int lane = tid & 31;
    const int g    = lane >> 2;
    const int tig  = lane & 3;

    const size_t base  = (size_t)b * S_ * D_ + (size_t)h * HD_;
    const size_t vbase = ((size_t)(b * H_ + h)) * HD_ * S_;

    // stage K tile (64 keys x 64 dims) + Vt tile (64 dims x 64 keys)
#define A_ISSUE(t, buf) do {                                               \
        const __half* Kb = K  + base + (size_t)((t) * 64) * D_;            \
        const __half* Vb = Vt + vbase + (t) * 64;                          \
        _Pragma("unroll")                                                  \
        for (int j = 0; j < 4; j++) {                                      \
            const int i = tid + 128 * j;                                   \
            const int row = i >> 3, ch = (i & 7) * 8;                      \
            cpa16(su + (OFF_K(buf) + row * KLDH + ch) * 2,                 \
                  Kb + (size_t)row * D_ + ch);                             \
            cpa16(su + (OFF_V(buf) + row * VLDH + ch) * 2,                 \
                  Vb + (size_t)row * S_ + ch);                             \
        }                                                                  \
        cpa_commit();                                                      \
    } while (0)

    {
        const __half* Qb = Q + base + (size_t)q0 * D_;
#pragma unroll
        for (int j = 0; j < 8; j++) {
            const int i = tid + 128 * j;          // 1024 chunks
            const int row = i >> 3, ch = (i & 7) * 8;
            cpa16(su + (row * QLDH + ch) * 2, Qb + (size_t)row * D_ + ch);
        }
        const __half* Kb = K + base;
        const __half* Vb = Vt + vbase;
#pragma unroll
        for (int j = 0; j < 4; j++) {
            const int i = tid + 128 * j;
            const int row = i >> 3, ch = (i & 7) * 8;
            cpa16(su + (OFF_K(0) + row * KLDH + ch) * 2, Kb + (size_t)row * D_ + ch);
            cpa16(su + (OFF_V(0) + row * VLDH + ch) * 2, Vb + (size_t)row * S_ + ch);
        }
        cpa_commit();
        A_ISSUE(1, 1);
    }

    float mrow[2][2], lrow[2][2];
#pragma unroll
    for (int mt = 0; mt < 2; mt++) {
        mrow[mt][0] = -1e30f; mrow[mt][1] = -1e30f;
        lrow[mt][0] = 0.f;    lrow[mt][1] = 0.f;
    }
    float o[2][8][4];
#pragma unroll
    for (int mt = 0; mt < 2; mt++)
#pragma unroll
        for (int nt = 0; nt < 8; nt++)
#pragma unroll
            for (int i = 0; i < 4; i++) o[mt][nt][i] = 0.f;

    const int NTILE = S_ / 64;   // 16
    for (int t = 0; t < NTILE; t++) {
        if (t == NTILE - 1) cpa_wait0(); else cpa_wait1();
        __syncthreads();

        const __half* sQ = smh;
        const __half* sK = smh + OFF_K(t & 1);
        const __half* sV = smh + OFF_V(t & 1);

        // ---- S = Q . K^T ----
        float s[2][8][4];
#pragma unroll
        for (int mt = 0; mt < 2; mt++)
#pragma unroll
            for (int nt = 0; nt < 8; nt++)
#pragma unroll
                for (int i = 0; i < 4; i++) s[mt][nt][i] = 0.f;

#pragma unroll
        for (int ks = 0; ks < 4; ks++) {
            uint2 alo[2], ahi[2];
#pragma unroll
            for (int mt = 0; mt < 2; mt++) {
                const int r0 = (w * 32 + mt * 16 + g) * QLDH + ks * 16 + 4 * tig;
                alo[mt] = *(const uint2*)&sQ[r0];
                ahi[mt] = *(const uint2*)&sQ[r0 + 8 * QLDH];
            }
#pragma unroll
            for (int nt = 0; nt < 8; nt++) {
                const uint2 bb = *(const uint2*)&sK[(nt * 8 + g) * KLDH
                                                    + ks * 16 + 4 * tig];
                mma_f16(s[0][nt], alo[0].x, ahi[0].x, alo[0].y, ahi[0].y, bb.x, bb.y);
                mma_f16(s[1][nt], alo[1].x, ahi[1].x, alo[1].y, ahi[1].y, bb.x, bb.y);
            }
        }

        // ---- online softmax (s -> P in place, fp32) ----
#pragma unroll
        for (int mt = 0; mt < 2; mt++) {
            float mx0 = -1e30f, mx1 = -1e30f;
#pragma unroll
            for (int nt = 0; nt < 8; nt++) {
                mx0 = fmaxf(mx0, fmaxf(s[mt][nt][0], s[mt][nt][1]));
                mx1 = fmaxf(mx1, fmaxf(s[mt][nt][2], s[mt][nt][3]));
            }
            mx0 = fmaxf(mx0, __shfl_xor_sync(0xffffffffu, mx0, 1));
            mx0 = fmaxf(mx0, __shfl_xor_sync(0xffffffffu, mx0, 2));
            mx1 = fmaxf(mx1, __shfl_xor_sync(0xffffffffu, mx1, 1));
            mx1 = fmaxf(mx1, __shfl_xor_sync(0xffffffffu, mx1, 2));

            const float nm0 = fmaxf(mrow[mt][0], mx0);
            const float nm1 = fmaxf(mrow[mt][1], mx1);
            const float al0 = __expf(mrow[mt][0] - nm0);
            const float al1 = __expf(mrow[mt][1] - nm1);
            mrow[mt][0] = nm0; mrow[mt][1] = nm1;

            float ps0 = 0.f, ps1 = 0.f;
#pragma unroll
            for (int nt = 0; nt < 8; nt++) {
                s[mt][nt][0] = __expf(s[mt][nt][0] - nm0);
                s[mt][nt][1] = __expf(s[mt][nt][1] - nm0);
                s[mt][nt][2] = __expf(s[mt][nt][2] - nm1);
                s[mt][nt][3] = __expf(s[mt][nt][3] - nm1);
                ps0 += s[mt][nt][0] + s[mt][nt][1];
                ps1 += s[mt][nt][2] + s[mt][nt][3];
            }
            ps0 += __shfl_xor_sync(0xffffffffu, ps0, 1);
            ps0 += __shfl_xor_sync(0xffffffffu, ps0, 2);
            ps1 += __shfl_xor_sync(0xffffffffu, ps1, 1);
            ps1 += __shfl_xor_sync(0xffffffffu, ps1, 2);
            lrow[mt][0] = lrow[mt][0] * al0 + ps0;
            lrow[mt][1] = lrow[mt][1] * al1 + ps1;

#pragma unroll
            for (int nt = 0; nt < 8; nt++) {
                o[mt][nt][0] *= al0; o[mt][nt][1] *= al0;
                o[mt][nt][2] *= al1; o[mt][nt][3] *= al1;
            }
        }

        // ---- O += P . V  (register-local P pack, Vt LDS.32 B-frags) ----
#pragma unroll
        for (int ks = 0; ks < 4; ks++) {
            uint32_t pa[2][4];
#pragma unroll
            for (int mt = 0; mt < 2; mt++) {
                pa[mt][0] = pack2(s[mt][2 * ks][0],     s[mt][2 * ks][1]);
                pa[mt][1] = pack2(s[mt][2 * ks][2],     s[mt][2 * ks][3]);
                pa[mt][2] = pack2(s[mt][2 * ks + 1][0], s[mt][2 * ks + 1][1]);
                pa[mt][3] = pack2(s[mt][2 * ks + 1][2], s[mt][2 * ks + 1][3]);
            }
#pragma unroll
            for (int nt = 0; nt < 8; nt++) {
                const int vr = (nt * 8 + g) * VLDH + ks * 16 + 2 * tig;
                const uint32_t b0 = *(const uint32_t*)&sV[vr];
                const uint32_t b1 = *(const uint32_t*)&sV[vr + 8];
                mma_f16(o[0][nt], pa[0][0], pa[0][1], pa[0][2], pa[0][3], b0, b1);
                mma_f16(o[1][nt], pa[1][0], pa[1][1], pa[1][2], pa[1][3], b0, b1);
            }
        }

        __syncthreads();
        if (t + 2 < NTILE) A_ISSUE(t + 2, t & 1);
    }
#undef A_ISSUE

    // ---- write out fp16, unit-permuted head-dim (feeds O-proj) ----
#pragma unroll
    for (int mt = 0; mt < 2; mt++) {
        const float inv0 = 1.f / lrow[mt][0];
        const float inv1 = 1.f / lrow[mt][1];
        const int row = q0 + w * 32 + mt * 16 + g;
#pragma unroll
        for (int nt = 0; nt < 8; nt++) {
            const int dsti = h * HD_ + (nt >> 1) * 16 + 4 * tig + 2 * (nt & 1);
            *(__half2*)(O + (size_t)(b * S_ + row) * D_ + dsti) =
                __floats2half2_rn(o[mt][nt][0] * inv0, o[mt][nt][1] * inv0);
            *(__half2*)(O + (size_t)(b * S_ + row + 8) * D_ + dsti) =
                __floats2half2_rn(o[mt][nt][2] * inv1, o[mt][nt][3] * inv1);
        }
    }
}

// ---------------------------------------------------------------------------
// Launch
// ---------------------------------------------------------------------------
extern "C" void kernel_launch(void* const* d_in, const int* in_sizes, int n_in,
                              void* d_out, int out_size)
{
    const float* x  = (const float*)d_in[0];
    const float* Wq = (const float*)d_in[1];
    const float* Wk = (const float*)d_in[2];
    const float* Wv = (const float*)d_in[3];
    const float* bq = (const float*)d_in[4];
    const float* bk = (const float*)d_in[5];
    const float* bv = (const float*)d_in[6];
    const float* Wo = (const float*)d_in[7];
    const float* bo = (const float*)d_in[8];
    float* out = (float*)d_out;

    __half *xh, *qh, *kh, *vt, *ch, *wqh, *wkh, *wvh, *woh;
    cudaGetSymbolAddress((void**)&xh,  g_xh);
    cudaGetSymbolAddress((void**)&qh,  g_qh);
    cudaGetSymbolAddress((void**)&kh,  g_kh);
    cudaGetSymbolAddress((void**)&vt,  g_vt);
    cudaGetSymbolAddress((void**)&ch,  g_ch);
    cudaGetSymbolAddress((void**)&wqh, g_wq);
    cudaGetSymbolAddress((void**)&wkh, g_wk);
    cudaGetSymbolAddress((void**)&wvh, g_wv);
    cudaGetSymbolAddress((void**)&woh, g_wo);

    cudaFuncSetAttribute(gemm_h,
                         cudaFuncAttributeMaxDynamicSharedMemorySize, GEMM_SMEM);
    cudaFuncSetAttribute(attn_h,
                         cudaFuncAttributeMaxDynamicSharedMemorySize, ATTN_SMEM);

    const int n4x = M_TOTAL * D_ / 4;
    const int n4w = D_ * D_ / 4;
    prep_h<<<(n4x + 255) / 256, 256>>>(x,  xh,  n4x);
    prep_h<<<(n4w + 255) / 256, 256>>>(Wq, wqh, n4w);
    prep_h<<<(n4w + 255) / 256, 256>>>(Wk, wkh, n4w);
    prep_h<<<(n4w + 255) / 256, 256>>>(Wv, wvh, n4w);
    prep_h<<<(n4w + 255) / 256, 256>>>(Wo, woh, n4w);

    // fused QKV: z=0 -> q (scale 0.125, perm fp16), z=1 -> k, z=2 -> Vt
    gemm_h<<<dim3(D_ / GBN, M_TOTAL / GBM, 3), 256, GEMM_SMEM>>>(
        xh, wqh, wkh, wvh, bq, bk, bv, qh, kh, vt, 0);

    attn_h<<<dim3(S_ / 128, H_, B_), 128, ATTN_SMEM>>>(qh, kh, vt, ch);

    // output projection: fp32 plain out
    gemm_h<<<dim3(D_ / GBN, M_TOTAL / GBM, 1), 256, GEMM_SMEM>>>(
        ch, woh, woh, woh, bo, bo, bo, out, out, out, 1);
}

// round 8
// speedup vs baseline: 1.7064x; 1.0100x over previous
#include <cuda_runtime.h>
#include <cuda_fp16.h>
#include <cstdint>
#include <math.h>

// ---------------------------------------------------------------------------
// MultiHeadAttention: B=8, S=1024, D=1024, H=16, HD=64
// Round 7: fp16 m16n8k16 pipeline. Changes vs round 6:
//  - single fused prep kernel (was 5 launches)
//  - attention Q fragments hoisted to registers (loaded once, not per tile)
//  - Vt key-dim unit-permuted -> PV B-fragments are single LDS.64
// ---------------------------------------------------------------------------

#define B_  8
#define S_  1024
#define D_  1024
#define H_  16
#define HD_ 64
#define M_TOTAL (B_ * S_)          // 8192

__device__ __half g_xh[(size_t)M_TOTAL * D_];
__device__ __half g_qh[(size_t)M_TOTAL * D_];
__device__ __half g_kh[(size_t)M_TOTAL * D_];
__device__ __half g_vt[(size_t)B_ * H_ * HD_ * S_];   // [B][H][d][key-perm]
__device__ __half g_ch[(size_t)M_TOTAL * D_];
__device__ __half g_wq[(size_t)D_ * D_];
__device__ __half g_wk[(size_t)D_ * D_];
__device__ __half g_wv[(size_t)D_ * D_];
__device__ __half g_wo[(size_t)D_ * D_];

// ---------------------------------------------------------------------------
// helpers
// ---------------------------------------------------------------------------
__device__ __forceinline__ uint32_t smem_u32(const void* p) {
    uint32_t a;
    asm("{ .reg .u64 t; cvta.to.shared.u64 t, %1; cvt.u32.u64 %0, t; }"
        : "=r"(a) : "l"(p));
    return a;
}

__device__ __forceinline__ void cpa16(uint32_t dst, const void* src) {
    asm volatile("cp.async.cg.shared.global [%0], [%1], 16;"
                 :: "r"(dst), "l"(src) : "memory");
}
__device__ __forceinline__ void cpa_commit() {
    asm volatile("cp.async.commit_group;" ::: "memory");
}
__device__ __forceinline__ void cpa_wait1() {
    asm volatile("cp.async.wait_group 1;" ::: "memory");
}
__device__ __forceinline__ void cpa_wait0() {
    asm volatile("cp.async.wait_group 0;" ::: "memory");
}

__device__ __forceinline__ void mma_f16(float* c,
                                        uint32_t a0, uint32_t a1, uint32_t a2, uint32_t a3,
                                        uint32_t b0, uint32_t b1) {
    asm volatile(
        "mma.sync.aligned.m16n8k16.row.col.f32.f16.f16.f32 "
        "{%0,%1,%2,%3}, {%4,%5,%6,%7}, {%8,%9}, {%0,%1,%2,%3};\n"
        : "+f"(c[0]), "+f"(c[1]), "+f"(c[2]), "+f"(c[3])
        : "r"(a0), "r"(a1), "r"(a2), "r"(a3), "r"(b0), "r"(b1));
}

__device__ __forceinline__ uint32_t pack2(float lo, float hi) {
    __half2 h = __floats2half2_rn(lo, hi);
    return *reinterpret_cast<uint32_t*>(&h);
}

// ---------------------------------------------------------------------------
// Fused pre-pass: fp16 convert + unit-permute (half2 units (u,u+4) adjacent)
// for x and the four weights in ONE launch.
// ---------------------------------------------------------------------------
#define N4X (M_TOTAL * D_ / 4)     // 2097152
#define N4W (D_ * D_ / 4)          // 262144

__global__ __launch_bounds__(256)
void prep_all(const float* __restrict__ x,
              const float* __restrict__ Wq, const float* __restrict__ Wk,
              const float* __restrict__ Wv, const float* __restrict__ Wo)
{
    const int i = blockIdx.x * blockDim.x + threadIdx.x;
    const float* src;
    __half* dst;
    int j;
    if (i < N4X)                  { src = x;  dst = g_xh; j = i; }
    else {
        const int r = i - N4X;
        const int w = r >> 18;    // / N4W
        j = r & (N4W - 1);
        if      (w == 0) { src = Wq; dst = g_wq; }
        else if (w == 1) { src = Wk; dst = g_wk; }
        else if (w == 2) { src = Wv; dst = g_wv; }
        else             { src = Wo; dst = g_wo; }
    }
    const float4 v = ((const float4*)src)[j];
    const int flat = j << 2;
    const int base = flat & ~15;
    const int u0   = (flat & 15) >> 1;           // 0,2,4,6
    const int p0   = ((u0 & 3) << 1) | (u0 >> 2);
    const int u1   = u0 + 1;
    const int p1   = ((u1 & 3) << 1) | (u1 >> 2);
    *(__half2*)(dst + base + 2 * p0) = __floats2half2_rn(v.x, v.y);
    *(__half2*)(dst + base + 2 * p1) = __floats2half2_rn(v.z, v.w);
}

// ---------------------------------------------------------------------------
// fp16 GEMM (NT): identical to round 6 except z==2 epilogue stores Vt at
// unit-permuted key positions.
// ---------------------------------------------------------------------------
#define GBM 256
#define GBN 128
#define GBKH 32
#define GLDH 80
#define GBUFH ((GBM + GBN) * GLDH)               // 30720 halves / buffer
#define GEMM_SMEM (3 * GBUFH * 2)                // 184320 bytes

__global__ __launch_bounds__(256, 1)
void gemm_h(const __half* __restrict__ A,
            const __half* __restrict__ W0, const __half* __restrict__ W1,
            const __half* __restrict__ W2,
            const float* __restrict__ bb0, const float* __restrict__ bb1,
            const float* __restrict__ bb2,
            void* C0, void* C1, void* C2,
            int oproj)
{
    extern __shared__ __half smh[];
    const int z = blockIdx.z;
    const __half* Bw   = (z == 0) ? W0  : (z == 1) ? W1  : W2;
    const float*  bias = (z == 0) ? bb0 : (z == 1) ? bb1 : bb2;
    void*         C    = (z == 0) ? C0  : (z == 1) ? C1  : C2;
    const float scale  = (!oproj && z == 0) ? 0.125f : 1.0f;

    const int tid  = threadIdx.x;
    const int wid  = tid >> 5;
    const int lane = tid & 31;
    const int g    = lane >> 2;
    const int tig  = lane & 3;
    const int wm   = (wid & 3) * 64;
    const int wn   = (wid >> 2) * 64;
    const int bm   = blockIdx.y * GBM;
    const int bn   = blockIdx.x * GBN;

    const __half* Abase = A  + (size_t)bm * D_;
    const __half* Bbase = Bw + (size_t)bn * D_;
    const uint32_t su   = smem_u32(smh);

#define G_ISSUE(slab) do {                                                 \
        const uint32_t s0 = su + (uint32_t)((slab) % 3) * (GBUFH * 2);     \
        const int k0 = (slab) * GBKH;                                      \
        _Pragma("unroll")                                                  \
        for (int j = 0; j < 4; j++) {                                      \
            const int i = tid + 256 * j;                                   \
            const int row = i >> 2, ch = (i & 3) * 8;                      \
            cpa16(s0 + (row * GLDH + ch) * 2,                              \
                  Abase + (size_t)row * D_ + k0 + ch);                     \
        }                                                                  \
        _Pragma("unroll")                                                  \
        for (int j = 0; j < 2; j++) {                                      \
            const int i = tid + 256 * j;                                   \
            const int row = i >> 2, ch = (i & 3) * 8;                      \
            cpa16(s0 + ((GBM + row) * GLDH + ch) * 2,                      \
                  Bbase + (size_t)row * D_ + k0 + ch);                     \
        }                                                                  \
        cpa_commit();                                                      \
    } while (0)

    float acc[4][8][4];
#pragma unroll
    for (int mt = 0; mt < 4; mt++)
#pragma unroll
        for (int nt = 0; nt < 8; nt++)
#pragma unroll
            for (int i = 0; i < 4; i++) acc[mt][nt][i] = 0.f;

    const int NT = D_ / GBKH;   // 32
    G_ISSUE(0);
    G_ISSUE(1);

    for (int t = 0; t < NT; t++) {
        if (t == NT - 1) cpa_wait0(); else cpa_wait1();
        __syncthreads();
        if (t + 2 < NT) G_ISSUE(t + 2);

        const __half* as = smh + (t % 3) * GBUFH;
        const __half* bs = as + GBM * GLDH;
#pragma unroll
        for (int ks = 0; ks < 2; ks++) {
            uint2 alo[4], ahi[4];
#pragma unroll
            for (int mt = 0; mt < 4; mt++) {
                const int r0 = (wm + mt * 16 + g) * GLDH + ks * 16 + 4 * tig;
                alo[mt] = *(const uint2*)&as[r0];
                ahi[mt] = *(const uint2*)&as[r0 + 8 * GLDH];
            }
#pragma unroll
            for (int nt = 0; nt < 8; nt++) {
                const uint2 bb = *(const uint2*)&bs[(wn + nt * 8 + g) * GLDH
                                                    + ks * 16 + 4 * tig];
#pragma unroll
                for (int mt = 0; mt < 4; mt++)
                    mma_f16(acc[mt][nt], alo[mt].x, ahi[mt].x, alo[mt].y, ahi[mt].y,
                            bb.x, bb.y);
            }
        }
    }
#undef G_ISSUE

    if (oproj) {
        float* Co = (float*)C;
#pragma unroll
        for (int mt = 0; mt < 4; mt++) {
            const int row0 = bm + wm + mt * 16 + g;
#pragma unroll
            for (int nt = 0; nt < 8; nt++) {
                const int col = bn + wn + nt * 8 + 2 * tig;
                const float c0 = bias[col], c1 = bias[col + 1];
                float2 v0 = make_float2(acc[mt][nt][0] + c0, acc[mt][nt][1] + c1);
                float2 v1 = make_float2(acc[mt][nt][2] + c0, acc[mt][nt][3] + c1);
                *(float2*)(Co + (size_t)row0 * D_ + col)       = v0;
                *(float2*)(Co + (size_t)(row0 + 8) * D_ + col) = v1;
            }
        }
    } else if (z < 2) {
        __half* Ch = (__half*)C;
#pragma unroll
        for (int mt = 0; mt < 4; mt++) {
            const int row0 = bm + wm + mt * 16 + g;
#pragma unroll
            for (int nt = 0; nt < 8; nt++) {
                const int n = bn + wn + nt * 8 + 2 * tig;
                const int dsti = bn + wn + (nt & ~1) * 8 + 4 * tig + 2 * (nt & 1);
                const float c0 = bias[n], c1 = bias[n + 1];
                *(__half2*)(Ch + (size_t)row0 * D_ + dsti) =
                    __floats2half2_rn((acc[mt][nt][0] + c0) * scale,
                                      (acc[mt][nt][1] + c1) * scale);
                *(__half2*)(Ch + (size_t)(row0 + 8) * D_ + dsti) =
                    __floats2half2_rn((acc[mt][nt][2] + c0) * scale,
                                      (acc[mt][nt][3] + c1) * scale);
            }
        }
    } else {
        // transposed Vt output with unit-permuted key positions:
        // key s -> (s & ~15) + 2*pos2((s>>1)&7) + (s&1)
        __half* Vt = (__half*)C;
#pragma unroll
        for (int mt = 0; mt < 4; mt++) {
            const int row0 = bm + wm + mt * 16 + g;
#pragma unroll
            for (int nt = 0; nt < 8; nt++) {
                const int n  = bn + wn + nt * 8 + 2 * tig;
                const float c0 = bias[n], c1 = bias[n + 1];
#pragma unroll
                for (int e = 0; e < 4; e++) {
                    const int row = row0 + (e >> 1) * 8;
                    const int col = n + (e & 1);
                    const float val = acc[mt][nt][e] + ((e & 1) ? c1 : c0);
                    const int bIdx = row >> 10, s = row & 1023;
                    const int u    = (s >> 1) & 7;
                    const int sp   = (s & ~15) + 2 * (((u & 3) << 1) | (u >> 2)) + (s & 1);
                    const int head = col >> 6,  dd = col & 63;
                    Vt[(((size_t)(bIdx * H_ + head)) * HD_ + dd) * S_ + sp] =
                        __float2half_rn(val);
                }
            }
        }
    }
}

// ---------------------------------------------------------------------------
// Flash attention, fp16 m16n8k16, cp.async double-buffered K/Vt, 2 CTAs/SM.
// Q fragments hoisted to registers (loaded once at t==0).
// Vt key-permuted -> PV B-frag is one LDS.64. Strides 80 (conflict-free).
// ---------------------------------------------------------------------------
#define QLDH 80
#define KLDH 80
#define VLDH 80
#define OFF_K(buf) (128 * QLDH + (buf) * 64 * KLDH)
#define OFF_V(buf) (128 * QLDH + 2 * 64 * KLDH + (buf) * 64 * VLDH)
#define ATTN_SMEM ((128 * QLDH + 2 * 64 * KLDH + 2 * 64 * VLDH) * 2)  // 61440 B

__global__ __launch_bounds__(128, 2)
void attn_h(const __half* __restrict__ Q, const __half* __restrict__ K,
            const __half* __restrict__ Vt, __half* __restrict__ O)
{
    extern __shared__ __half smh[];
    const uint32_t su = smem_u32(smh);

    const int q0   = blockIdx.x * 128;
    const int h    = blockIdx.y;
    const int b    = blockIdx.z;
    const int tid  = threadIdx.x;
    const int w    = tid >> 5;
    const int lane = tid & 31;
    const int g    = lane >> 2;
    const int tig  = lane & 3;

    const size_t base  = (size_t)b * S_ * D_ + (size_t)h * HD_;
    const size_t vbase = ((size_t)(b * H_ + h)) * HD_ * S_;

#define A_ISSUE(t, buf) do {                                               \
        const __half* Kb = K  + base + (size_t)((t) * 64) * D_;            \
        const __half* Vb = Vt + vbase + (t) * 64;                          \
        _Pragma("unroll")                                                  \
        for (int j = 0; j < 4; j++) {                                      \
            const int i = tid + 128 * j;                                   \
            const int row = i >> 3, ch = (i & 7) * 8;                      \
            cpa16(su + (OFF_K(buf) + row * KLDH + ch) * 2,                 \
                  Kb + (size_t)row * D_ + ch);                             \
            cpa16(su + (OFF_V(buf) + row * VLDH + ch) * 2,                 \
                  Vb + (size_t)row * S_ + ch);                             \
        }                                                                  \
        cpa_commit();                                                      \
    } while (0)

    {
        const __half* Qb = Q + base + (size_t)q0 * D_;
#pragma unroll
        for (int j = 0; j < 8; j++) {
            const int i = tid + 128 * j;
            const int row = i >> 3, ch = (i & 7) * 8;
            cpa16(su + (row * QLDH + ch) * 2, Qb + (size_t)row * D_ + ch);
        }
        const __half* Kb = K + base;
        const __half* Vb = Vt + vbase;
#pragma unroll
        for (int j = 0; j < 4; j++) {
            const int i = tid + 128 * j;
            const int row = i >> 3, ch = (i & 7) * 8;
            cpa16(su + (OFF_K(0) + row * KLDH + ch) * 2, Kb + (size_t)row * D_ + ch);
            cpa16(su + (OFF_V(0) + row * VLDH + ch) * 2, Vb + (size_t)row * S_ + ch);
        }
        cpa_commit();
        A_ISSUE(1, 1);
    }

    float mrow[2][2], lrow[2][2];
#pragma unroll
    for (int mt = 0; mt < 2; mt++) {
        mrow[mt][0] = -1e30f; mrow[mt][1] = -1e30f;
        lrow[mt][0] = 0.f;    lrow[mt][1] = 0.f;
    }
    float o[2][8][4];
#pragma unroll
    for (int mt = 0; mt < 2; mt++)
#pragma unroll
        for (int nt = 0; nt < 8; nt++)
#pragma unroll
            for (int i = 0; i < 4; i++) o[mt][nt][i] = 0.f;

    uint2 qlo[2][4], qhi[2][4];   // hoisted Q fragments

    const int NTILE = S_ / 64;   // 16
    for (int t = 0; t < NTILE; t++) {
        if (t == NTILE - 1) cpa_wait0(); else cpa_wait1();
        __syncthreads();

        if (t == 0) {
            // hoist Q fragments once (sQ region is never overwritten)
#pragma unroll
            for (int ks = 0; ks < 4; ks++)
#pragma unroll
                for (int mt = 0; mt < 2; mt++) {
                    const int r0 = (w * 32 + mt * 16 + g) * QLDH + ks * 16 + 4 * tig;
                    qlo[mt][ks] = *(const uint2*)&smh[r0];
                    qhi[mt][ks] = *(const uint2*)&smh[r0 + 8 * QLDH];
                }
        }

        const __half* sK = smh + OFF_K(t & 1);
        const __half* sV = smh + OFF_V(t & 1);

        // ---- S = Q . K^T ----
        float s[2][8][4];
#pragma unroll
        for (int mt = 0; mt < 2; mt++)
#pragma unroll
            for (int nt = 0; nt < 8; nt++)
#pragma unroll
                for (int i = 0; i < 4; i++) s[mt][nt][i] = 0.f;

#pragma unroll
        for (int ks = 0; ks < 4; ks++) {
#pragma unroll
            for (int nt = 0; nt < 8; nt++) {
                const uint2 bb = *(const uint2*)&sK[(nt * 8 + g) * KLDH
                                                    + ks * 16 + 4 * tig];
                mma_f16(s[0][nt], qlo[0][ks].x, qhi[0][ks].x, qlo[0][ks].y,
                        qhi[0][ks].y, bb.x, bb.y);
                mma_f16(s[1][nt], qlo[1][ks].x, qhi[1][ks].x, qlo[1][ks].y,
                        qhi[1][ks].y, bb.x, bb.y);
            }
        }

        // ---- online softmax (s -> P in place, fp32) ----
#pragma unroll
        for (int mt = 0; mt < 2; mt++) {
            float mx0 = -1e30f, mx1 = -1e30f;
#pragma unroll
            for (int nt = 0; nt < 8; nt++) {
                mx0 = fmaxf(mx0, fmaxf(s[mt][nt][0], s[mt][nt][1]));
                mx1 = fmaxf(mx1, fmaxf(s[mt][nt][2], s[mt][nt][3]));
            }
            mx0 = fmaxf(mx0, __shfl_xor_sync(0xffffffffu, mx0, 1));
            mx0 = fmaxf(mx0, __shfl_xor_sync(0xffffffffu, mx0, 2));
            mx1 = fmaxf(mx1, __shfl_xor_sync(0xffffffffu, mx1, 1));
            mx1 = fmaxf(mx1, __shfl_xor_sync(0xffffffffu, mx1, 2));

            const float nm0 = fmaxf(mrow[mt][0], mx0);
            const float nm1 = fmaxf(mrow[mt][1], mx1);
            const float al0 = __expf(mrow[mt][0] - nm0);
            const float al1 = __expf(mrow[mt][1] - nm1);
            mrow[mt][0] = nm0; mrow[mt][1] = nm1;

            float ps0 = 0.f, ps1 = 0.f;
#pragma unroll
            for (int nt = 0; nt < 8; nt++) {
                s[mt][nt][0] = __expf(s[mt][nt][0] - nm0);
                s[mt][nt][1] = __expf(s[mt][nt][1] - nm0);
                s[mt][nt][2] = __expf(s[mt][nt][2] - nm1);
                s[mt][nt][3] = __expf(s[mt][nt][3] - nm1);
                ps0 += s[mt][nt][0] + s[mt][nt][1];
                ps1 += s[mt][nt][2] + s[mt][nt][3];
            }
            ps0 += __shfl_xor_sync(0xffffffffu, ps0, 1);
            ps0 += __shfl_xor_sync(0xffffffffu, ps0, 2);
            ps1 += __shfl_xor_sync(0xffffffffu, ps1, 1);
            ps1 += __shfl_xor_sync(0xffffffffu, ps1, 2);
            lrow[mt][0] = lrow[mt][0] * al0 + ps0;
            lrow[mt][1] = lrow[mt][1] * al1 + ps1;

#pragma unroll
            for (int nt = 0; nt < 8; nt++) {
                o[mt][nt][0] *= al0; o[mt][nt][1] *= al0;
                o[mt][nt][2] *= al1; o[mt][nt][3] *= al1;
            }
        }

        // ---- O += P . V  (register-local P pack; Vt key-perm LDS.64) ----
#pragma unroll
        for (int ks = 0; ks < 4; ks++) {
            uint32_t pa[2][4];
#pragma unroll
            for (int mt = 0; mt < 2; mt++) {
                pa[mt][0] = pack2(s[mt][2 * ks][0],     s[mt][2 * ks][1]);
                pa[mt][1] = pack2(s[mt][2 * ks][2],     s[mt][2 * ks][3]);
                pa[mt][2] = pack2(s[mt][2 * ks + 1][0], s[mt][2 * ks + 1][1]);
                pa[mt][3] = pack2(s[mt][2 * ks + 1][2], s[mt][2 * ks + 1][3]);
            }
#pragma unroll
            for (int nt = 0; nt < 8; nt++) {
                const uint2 bb = *(const uint2*)&sV[(nt * 8 + g) * VLDH
                                                    + ks * 16 + 4 * tig];
                mma_f16(o[0][nt], pa[0][0], pa[0][1], pa[0][2], pa[0][3], bb.x, bb.y);
                mma_f16(o[1][nt], pa[1][0], pa[1][1], pa[1][2], pa[1][3], bb.x, bb.y);
            }
        }

        __syncthreads();
        if (t + 2 < NTILE) A_ISSUE(t + 2, t & 1);
    }
#undef A_ISSUE

    // ---- write out fp16, unit-permuted head-dim (feeds O-proj) ----
#pragma unroll
    for (int mt = 0; mt < 2; mt++) {
        const float inv0 = 1.f / lrow[mt][0];
        const float inv1 = 1.f / lrow[mt][1];
        const int row = q0 + w * 32 + mt * 16 + g;
#pragma unroll
        for (int nt = 0; nt < 8; nt++) {
            const int dsti = h * HD_ + (nt >> 1) * 16 + 4 * tig + 2 * (nt & 1);
            *(__half2*)(O + (size_t)(b * S_ + row) * D_ + dsti) =
                __floats2half2_rn(o[mt][nt][0] * inv0, o[mt][nt][1] * inv0);
            *(__half2*)(O + (size_t)(b * S_ + row + 8) * D_ + dsti) =
                __floats2half2_rn(o[mt][nt][2] * inv1, o[mt][nt][3] * inv1);
        }
    }
}

// ---------------------------------------------------------------------------
// Launch
// ---------------------------------------------------------------------------
extern "C" void kernel_launch(void* const* d_in, const int* in_sizes, int n_in,
                              void* d_out, int out_size)
{
    const float* x  = (const float*)d_in[0];
    const float* Wq = (const float*)d_in[1];
    const float* Wk = (const float*)d_in[2];
    const float* Wv = (const float*)d_in[3];
    const float* bq = (const float*)d_in[4];
    const float* bk = (const float*)d_in[5];
    const float* bv = (const float*)d_in[6];
    const float* Wo = (const float*)d_in[7];
    const float* bo = (const float*)d_in[8];
    float* out = (float*)d_out;

    __half *xh, *qh, *kh, *vt, *ch, *wqh, *wkh, *wvh, *woh;
    cudaGetSymbolAddress((void**)&xh,  g_xh);
    cudaGetSymbolAddress((void**)&qh,  g_qh);
    cudaGetSymbolAddress((void**)&kh,  g_kh);
    cudaGetSymbolAddress((void**)&vt,  g_vt);
    cudaGetSymbolAddress((void**)&ch,  g_ch);
    cudaGetSymbolAddress((void**)&wqh, g_wq);
    cudaGetSymbolAddress((void**)&wkh, g_wk);
    cudaGetSymbolAddress((void**)&wvh, g_wv);
    cudaGetSymbolAddress((void**)&woh, g_wo);

    cudaFuncSetAttribute(gemm_h,
                         cudaFuncAttributeMaxDynamicSharedMemorySize, GEMM_SMEM);
    cudaFuncSetAttribute(attn_h,
                         cudaFuncAttributeMaxDynamicSharedMemorySize, ATTN_SMEM);

    // single fused prep launch over x + 4 weights
    const int n4all = N4X + 4 * N4W;   // 3145728
    prep_all<<<n4all / 256, 256>>>(x, Wq, Wk, Wv, Wo);

    // fused QKV: z=0 -> q (scale 0.125), z=1 -> k, z=2 -> Vt (key-permuted)
    gemm_h<<<dim3(D_ / GBN, M_TOTAL / GBM, 3), 256, GEMM_SMEM>>>(
        xh, wqh, wkh, wvh, bq, bk, bv, qh, kh, vt, 0);

    attn_h<<<dim3(S_ / 128, H_, B_), 128, ATTN_SMEM>>>(qh, kh, vt, ch);

    // output projection: fp32 plain out
    gemm_h<<<dim3(D_ / GBN, M_TOTAL / GBM, 1), 256, GEMM_SMEM>>>(
        ch, woh, woh, woh, bo, bo, bo, out, out, out, 1);
}

// round 9
// speedup vs baseline: 1.8781x; 1.1007x over previous
#include <cuda_runtime.h>
#include <cuda_fp16.h>
#include <cstdint>
#include <math.h>

// ---------------------------------------------------------------------------
// MultiHeadAttention: B=8, S=1024, D=1024, H=16, HD=64
// Round 8: GEMM re-tiled for occupancy: 128x128 CTA tile, 32x64 warp tile
// (64 acc regs/thread), 2-buffer cp.async ring (80KB smem) -> 2 CTAs/SM.
// Attention and prep unchanged from round 7.
// ---------------------------------------------------------------------------

#define B_  8
#define S_  1024
#define D_  1024
#define H_  16
#define HD_ 64
#define M_TOTAL (B_ * S_)          // 8192

__device__ __half g_xh[(size_t)M_TOTAL * D_];
__device__ __half g_qh[(size_t)M_TOTAL * D_];
__device__ __half g_kh[(size_t)M_TOTAL * D_];
__device__ __half g_vt[(size_t)B_ * H_ * HD_ * S_];   // [B][H][d][key-perm]
__device__ __half g_ch[(size_t)M_TOTAL * D_];
__device__ __half g_wq[(size_t)D_ * D_];
__device__ __half g_wk[(size_t)D_ * D_];
__device__ __half g_wv[(size_t)D_ * D_];
__device__ __half g_wo[(size_t)D_ * D_];

// ---------------------------------------------------------------------------
// helpers
// ---------------------------------------------------------------------------
__device__ __forceinline__ uint32_t smem_u32(const void* p) {
    uint32_t a;
    asm("{ .reg .u64 t; cvta.to.shared.u64 t, %1; cvt.u32.u64 %0, t; }"
        : "=r"(a) : "l"(p));
    return a;
}

__device__ __forceinline__ void cpa16(uint32_t dst, const void* src) {
    asm volatile("cp.async.cg.shared.global [%0], [%1], 16;"
                 :: "r"(dst), "l"(src) : "memory");
}
__device__ __forceinline__ void cpa_commit() {
    asm volatile("cp.async.commit_group;" ::: "memory");
}
__device__ __forceinline__ void cpa_wait1() {
    asm volatile("cp.async.wait_group 1;" ::: "memory");
}
__device__ __forceinline__ void cpa_wait0() {
    asm volatile("cp.async.wait_group 0;" ::: "memory");
}

__device__ __forceinline__ void mma_f16(float* c,
                                        uint32_t a0, uint32_t a1, uint32_t a2, uint32_t a3,
                                        uint32_t b0, uint32_t b1) {
    asm volatile(
        "mma.sync.aligned.m16n8k16.row.col.f32.f16.f16.f32 "
        "{%0,%1,%2,%3}, {%4,%5,%6,%7}, {%8,%9}, {%0,%1,%2,%3};\n"
        : "+f"(c[0]), "+f"(c[1]), "+f"(c[2]), "+f"(c[3])
        : "r"(a0), "r"(a1), "r"(a2), "r"(a3), "r"(b0), "r"(b1));
}

__device__ __forceinline__ uint32_t pack2(float lo, float hi) {
    __half2 h = __floats2half2_rn(lo, hi);
    return *reinterpret_cast<uint32_t*>(&h);
}

// ---------------------------------------------------------------------------
// Fused pre-pass (round 7, unchanged)
// ---------------------------------------------------------------------------
#define N4X (M_TOTAL * D_ / 4)     // 2097152
#define N4W (D_ * D_ / 4)          // 262144

__global__ __launch_bounds__(256)
void prep_all(const float* __restrict__ x,
              const float* __restrict__ Wq, const float* __restrict__ Wk,
              const float* __restrict__ Wv, const float* __restrict__ Wo)
{
    const int i = blockIdx.x * blockDim.x + threadIdx.x;
    const float* src;
    __half* dst;
    int j;
    if (i < N4X)                  { src = x;  dst = g_xh; j = i; }
    else {
        const int r = i - N4X;
        const int w = r >> 18;
        j = r & (N4W - 1);
        if      (w == 0) { src = Wq; dst = g_wq; }
        else if (w == 1) { src = Wk; dst = g_wk; }
        else if (w == 2) { src = Wv; dst = g_wv; }
        else             { src = Wo; dst = g_wo; }
    }
    const float4 v = ((const float4*)src)[j];
    const int flat = j << 2;
    const int base = flat & ~15;
    const int u0   = (flat & 15) >> 1;
    const int p0   = ((u0 & 3) << 1) | (u0 >> 2);
    const int u1   = u0 + 1;
    const int p1   = ((u1 & 3) << 1) | (u1 >> 2);
    *(__half2*)(dst + base + 2 * p0) = __floats2half2_rn(v.x, v.y);
    *(__half2*)(dst + base + 2 * p1) = __floats2half2_rn(v.z, v.w);
}

// ---------------------------------------------------------------------------
// fp16 GEMM (NT): CTA 128x128, BK=32, 8 warps of 32x64 (acc = 64 regs),
// 2-buffer cp.async ring, 2 CTAs/SM. Stride 80 halves (conflict-free).
// ---------------------------------------------------------------------------
#define GBM 128
#define GBN 128
#define GBKH 32
#define GLDH 80
#define GBUFH ((GBM + GBN) * GLDH)               // 20480 halves / buffer
#define GEMM_SMEM (2 * GBUFH * 2)                // 81920 bytes

__global__ __launch_bounds__(256, 2)
void gemm_h(const __half* __restrict__ A,
            const __half* __restrict__ W0, const __half* __restrict__ W1,
            const __half* __restrict__ W2,
            const float* __restrict__ bb0, const float* __restrict__ bb1,
            const float* __restrict__ bb2,
            void* C0, void* C1, void* C2,
            int oproj)
{
    extern __shared__ __half smh[];
    const int z = blockIdx.z;
    const __half* Bw   = (z == 0) ? W0  : (z == 1) ? W1  : W2;
    const float*  bias = (z == 0) ? bb0 : (z == 1) ? bb1 : bb2;
    void*         C    = (z == 0) ? C0  : (z == 1) ? C1  : C2;
    const float scale  = (!oproj && z == 0) ? 0.125f : 1.0f;

    const int tid  = threadIdx.x;
    const int wid  = tid >> 5;
    const int lane = tid & 31;
    const int g    = lane >> 2;
    const int tig  = lane & 3;
    const int wm   = (wid & 3) * 32;     // 4 warps cover 128 m-rows
    const int wn   = (wid >> 2) * 64;    // 2 warps cover 128 n-cols
    const int bm   = blockIdx.y * GBM;
    const int bn   = blockIdx.x * GBN;

    const __half* Abase = A  + (size_t)bm * D_;
    const __half* Bbase = Bw + (size_t)bn * D_;
    const uint32_t su   = smem_u32(smh);

    // stage one BK=32 slab (A: 128x32, B: 128x32) into buffer `buf`
#define G_ISSUE(slab, buf) do {                                            \
        const uint32_t s0 = su + (uint32_t)(buf) * (GBUFH * 2);            \
        const int k0 = (slab) * GBKH;                                      \
        _Pragma("unroll")                                                  \
        for (int j = 0; j < 2; j++) {                                      \
            const int i = tid + 256 * j;       /* A: 512 16B chunks */     \
            const int row = i >> 2, ch = (i & 3) * 8;                      \
            cpa16(s0 + (row * GLDH + ch) * 2,                              \
                  Abase + (size_t)row * D_ + k0 + ch);                     \
        }                                                                  \
        _Pragma("unroll")                                                  \
        for (int j = 0; j < 2; j++) {                                      \
            const int i = tid + 256 * j;       /* B: 512 16B chunks */     \
            const int row = i >> 2, ch = (i & 3) * 8;                      \
            cpa16(s0 + ((GBM + row) * GLDH + ch) * 2,                      \
                  Bbase + (size_t)row * D_ + k0 + ch);                     \
        }                                                                  \
        cpa_commit();                                                      \
    } while (0)

    float acc[2][8][4];
#pragma unroll
    for (int mt = 0; mt < 2; mt++)
#pragma unroll
        for (int nt = 0; nt < 8; nt++)
#pragma unroll
            for (int i = 0; i < 4; i++) acc[mt][nt][i] = 0.f;

    const int NT = D_ / GBKH;   // 32
    G_ISSUE(0, 0);
    G_ISSUE(1, 1);

    for (int t = 0; t < NT; t++) {
        if (t == NT - 1) cpa_wait0(); else cpa_wait1();
        __syncthreads();

        const __half* as = smh + (t & 1) * GBUFH;
        const __half* bs = as + GBM * GLDH;
#pragma unroll
        for (int ks = 0; ks < 2; ks++) {
            uint2 alo[2], ahi[2];
#pragma unroll
            for (int mt = 0; mt < 2; mt++) {
                const int r0 = (wm + mt * 16 + g) * GLDH + ks * 16 + 4 * tig;
                alo[mt] = *(const uint2*)&as[r0];
                ahi[mt] = *(const uint2*)&as[r0 + 8 * GLDH];
            }
#pragma unroll
            for (int nt = 0; nt < 8; nt++) {
                const uint2 bb = *(const uint2*)&bs[(wn + nt * 8 + g) * GLDH
                                                    + ks * 16 + 4 * tig];
#pragma unroll
                for (int mt = 0; mt < 2; mt++)
                    mma_f16(acc[mt][nt], alo[mt].x, ahi[mt].x, alo[mt].y, ahi[mt].y,
                            bb.x, bb.y);
            }
        }
        __syncthreads();                 // compute done before reissue
        if (t + 2 < NT) G_ISSUE(t + 2, t & 1);
    }
#undef G_ISSUE

    if (oproj) {
        float* Co = (float*)C;
#pragma unroll
        for (int mt = 0; mt < 2; mt++) {
            const int row0 = bm + wm + mt * 16 + g;
#pragma unroll
            for (int nt = 0; nt < 8; nt++) {
                const int col = bn + wn + nt * 8 + 2 * tig;
                const float c0 = bias[col], c1 = bias[col + 1];
                float2 v0 = make_float2(acc[mt][nt][0] + c0, acc[mt][nt][1] + c1);
                float2 v1 = make_float2(acc[mt][nt][2] + c0, acc[mt][nt][3] + c1);
                *(float2*)(Co + (size_t)row0 * D_ + col)       = v0;
                *(float2*)(Co + (size_t)(row0 + 8) * D_ + col) = v1;
            }
        }
    } else if (z < 2) {
        __half* Ch = (__half*)C;
#pragma unroll
        for (int mt = 0; mt < 2; mt++) {
            const int row0 = bm + wm + mt * 16 + g;
#pragma unroll
            for (int nt = 0; nt < 8; nt++) {
                const int n = bn + wn + nt * 8 + 2 * tig;
                const int dsti = bn + wn + (nt & ~1) * 8 + 4 * tig + 2 * (nt & 1);
                const float c0 = bias[n], c1 = bias[n + 1];
                *(__half2*)(Ch + (size_t)row0 * D_ + dsti) =
                    __floats2half2_rn((acc[mt][nt][0] + c0) * scale,
                                      (acc[mt][nt][1] + c1) * scale);
                *(__half2*)(Ch + (size_t)(row0 + 8) * D_ + dsti) =
                    __floats2half2_rn((acc[mt][nt][2] + c0) * scale,
                                      (acc[mt][nt][3] + c1) * scale);
            }
        }
    } else {
        // transposed Vt output with unit-permuted key positions
        __half* Vt = (__half*)C;
#pragma unroll
        for (int mt = 0; mt < 2; mt++) {
            const int row0 = bm + wm + mt * 16 + g;
#pragma unroll
            for (int nt = 0; nt < 8; nt++) {
                const int n  = bn + wn + nt * 8 + 2 * tig;
                const float c0 = bias[n], c1 = bias[n + 1];
#pragma unroll
                for (int e = 0; e < 4; e++) {
                    const int row = row0 + (e >> 1) * 8;
                    const int col = n + (e & 1);
                    const float val = acc[mt][nt][e] + ((e & 1) ? c1 : c0);
                    const int bIdx = row >> 10, s = row & 1023;
                    const int u    = (s >> 1) & 7;
                    const int sp   = (s & ~15) + 2 * (((u & 3) << 1) | (u >> 2)) + (s & 1);
                    const int head = col >> 6,  dd = col & 63;
                    Vt[(((size_t)(bIdx * H_ + head)) * HD_ + dd) * S_ + sp] =
                        __float2half_rn(val);
                }
            }
        }
    }
}

// ---------------------------------------------------------------------------
// Flash attention (round 7, unchanged): fp16 m16n8k16, cp.async double-
// buffered K/Vt, 2 CTAs/SM, Q frags hoisted, Vt key-permuted LDS.64 B-frags.
// ---------------------------------------------------------------------------
#define QLDH 80
#define KLDH 80
#define VLDH 80
#define OFF_K(buf) (128 * QLDH + (buf) * 64 * KLDH)
#define OFF_V(buf) (128 * QLDH + 2 * 64 * KLDH + (buf) * 64 * VLDH)
#define ATTN_SMEM ((128 * QLDH + 2 * 64 * KLDH + 2 * 64 * VLDH) * 2)  // 61440 B

__global__ __launch_bounds__(128, 2)
void attn_h(const __half* __restrict__ Q, const __half* __restrict__ K,
            const __half* __restrict__ Vt, __half* __restrict__ O)
{
    extern __shared__ __half smh[];
    const uint32_t su = smem_u32(smh);

    const int q0   = blockIdx.x * 128;
    const int h    = blockIdx.y;
    const int b    = blockIdx.z;
    const int tid  = threadIdx.x;
    const int w    = tid >> 5;
    const int lane = tid & 31;
    const int g    = lane >> 2;
    const int tig  = lane & 3;

    const size_t base  = (size_t)b * S_ * D_ + (size_t)h * HD_;
    const size_t vbase = ((size_t)(b * H_ + h)) * HD_ * S_;

#define A_ISSUE(t, buf) do {                                               \
        const __half* Kb = K  + base + (size_t)((t) * 64) * D_;            \
        const __half* Vb = Vt + vbase + (t) * 64;                          \
        _Pragma("unroll")                                                  \
        for (int j = 0; j < 4; j++) {                                      \
            const int i = tid + 128 * j;                                   \
            const int row = i >> 3, ch = (i & 7) * 8;                      \
            cpa16(su + (OFF_K(buf) + row * KLDH + ch) * 2,                 \
                  Kb + (size_t)row * D_ + ch);                             \
            cpa16(su + (OFF_V(buf) + row * VLDH + ch) * 2,                 \
                  Vb + (size_t)row * S_ + ch);                             \
        }                                                                  \
        cpa_commit();                                                      \
    } while (0)

    {
        const __half* Qb = Q + base + (size_t)q0 * D_;
#pragma unroll
        for (int j = 0; j < 8; j++) {
            const int i = tid + 128 * j;
            const int row = i >> 3, ch = (i & 7) * 8;
            cpa16(su + (row * QLDH + ch) * 2, Qb + (size_t)row * D_ + ch);
        }
        const __half* Kb = K + base;
        const __half* Vb = Vt + vbase;
#pragma unroll
        for (int j = 0; j < 4; j++) {
            const int i = tid + 128 * j;
            const int row = i >> 3, ch = (i & 7) * 8;
            cpa16(su + (OFF_K(0) + row * KLDH + ch) * 2, Kb + (size_t)row * D_ + ch);
            cpa16(su + (OFF_V(0) + row * VLDH + ch) * 2, Vb + (size_t)row * S_ + ch);
        }
        cpa_commit();
        A_ISSUE(1, 1);
    }

    float mrow[2][2], lrow[2][2];
#pragma unroll
    for (int mt = 0; mt < 2; mt++) {
        mrow[mt][0] = -1e30f; mrow[mt][1] = -1e30f;
        lrow[mt][0] = 0.f;    lrow[mt][1] = 0.f;
    }
    float o[2][8][4];
#pragma unroll
    for (int mt = 0; mt < 2; mt++)
#pragma unroll
        for (int nt = 0; nt < 8; nt++)
#pragma unroll
            for (int i = 0; i < 4; i++) o[mt][nt][i] = 0.f;

    uint2 qlo[2][4], qhi[2][4];

    const int NTILE = S_ / 64;   // 16
    for (int t = 0; t < NTILE; t++) {
        if (t == NTILE - 1) cpa_wait0(); else cpa_wait1();
        __syncthreads();

        if (t == 0) {
#pragma unroll
            for (int ks = 0; ks < 4; ks++)
#pragma unroll
                for (int mt = 0; mt < 2; mt++) {
                    const int r0 = (w * 32 + mt * 16 + g) * QLDH + ks * 16 + 4 * tig;
                    qlo[mt][ks] = *(const uint2*)&smh[r0];
                    qhi[mt][ks] = *(const uint2*)&smh[r0 + 8 * QLDH];
                }
        }

        const __half* sK = smh + OFF_K(t & 1);
        const __half* sV = smh + OFF_V(t & 1);

        float s[2][8][4];
#pragma unroll
        for (int mt = 0; mt < 2; mt++)
#pragma unroll
            for (int nt = 0; nt < 8; nt++)
#pragma unroll
                for (int i = 0; i < 4; i++) s[mt][nt][i] = 0.f;

#pragma unroll
        for (int ks = 0; ks < 4; ks++) {
#pragma unroll
            for (int nt = 0; nt < 8; nt++) {
                const uint2 bb = *(const uint2*)&sK[(nt * 8 + g) * KLDH
                                                    + ks * 16 + 4 * tig];
                mma_f16(s[0][nt], qlo[0][ks].x, qhi[0][ks].x, qlo[0][ks].y,
                        qhi[0][ks].y, bb.x, bb.y);
                mma_f16(s[1][nt], qlo[1][ks].x, qhi[1][ks].x, qlo[1][ks].y,
                        qhi[1][ks].y, bb.x, bb.y);
            }
        }

#pragma unroll
        for (int mt = 0; mt < 2; mt++) {
            float mx0 = -1e30f, mx1 = -1e30f;
#pragma unroll
            for (int nt = 0; nt < 8; nt++) {
                mx0 = fmaxf(mx0, fmaxf(s[mt][nt][0], s[mt][nt][1]));
                mx1 = fmaxf(mx1, fmaxf(s[mt][nt][2], s[mt][nt][3]));
            }
            mx0 = fmaxf(mx0, __shfl_xor_sync(0xffffffffu, mx0, 1));
            mx0 = fmaxf(mx0, __shfl_xor_sync(0xffffffffu, mx0, 2));
            mx1 = fmaxf(mx1, __shfl_xor_sync(0xffffffffu, mx1, 1));
            mx1 = fmaxf(mx1, __shfl_xor_sync(0xffffffffu, mx1, 2));

            const float nm0 = fmaxf(mrow[mt][0], mx0);
            const float nm1 = fmaxf(mrow[mt][1], mx1);
            const float al0 = __expf(mrow[mt][0] - nm0);
            const float al1 = __expf(mrow[mt][1] - nm1);
            mrow[mt][0] = nm0; mrow[mt][1] = nm1;

            float ps0 = 0.f, ps1 = 0.f;
#pragma unroll
            for (int nt = 0; nt < 8; nt++) {
                s[mt][nt][0] = __expf(s[mt][nt][0] - nm0);
                s[mt][nt][1] = __expf(s[mt][nt][1] - nm0);
                s[mt][nt][2] = __expf(s[mt][nt][2] - nm1);
                s[mt][nt][3] = __expf(s[mt][nt][3] - nm1);
                ps0 += s[mt][nt][0] + s[mt][nt][1];
                ps1 += s[mt][nt][2] + s[mt][nt][3];
            }
            ps0 += __shfl_xor_sync(0xffffffffu, ps0, 1);
            ps0 += __shfl_xor_sync(0xffffffffu, ps0, 2);
            ps1 += __shfl_xor_sync(0xffffffffu, ps1, 1);
            ps1 += __shfl_xor_sync(0xffffffffu, ps1, 2);
            lrow[mt][0] = lrow[mt][0] * al0 + ps0;
            lrow[mt][1] = lrow[mt][1] * al1 + ps1;

#pragma unroll
            for (int nt = 0; nt < 8; nt++) {
                o[mt][nt][0] *= al0; o[mt][nt][1] *= al0;
                o[mt][nt][2] *= al1; o[mt][nt][3] *= al1;
            }
        }

#pragma unroll
        for (int ks = 0; ks < 4; ks++) {
            uint32_t pa[2][4];
#pragma unroll
            for (int mt = 0; mt < 2; mt++) {
                pa[mt][0] = pack2(s[mt][2 * ks][0],     s[mt][2 * ks][1]);
                pa[mt][1] = pack2(s[mt][2 * ks][2],     s[mt][2 * ks][3]);
                pa[mt][2] = pack2(s[mt][2 * ks + 1][0], s[mt][2 * ks + 1][1]);
                pa[mt][3] = pack2(s[mt][2 * ks + 1][2], s[mt][2 * ks + 1][3]);
            }
#pragma unroll
            for (int nt = 0; nt < 8; nt++) {
                const uint2 bb = *(const uint2*)&sV[(nt * 8 + g) * VLDH
                                                    + ks * 16 + 4 * tig];
                mma_f16(o[0][nt], pa[0][0], pa[0][1], pa[0][2], pa[0][3], bb.x, bb.y);
                mma_f16(o[1][nt], pa[1][0], pa[1][1], pa[1][2], pa[1][3], bb.x, bb.y);
            }
        }

        __syncthreads();
        if (t + 2 < NTILE) A_ISSUE(t + 2, t & 1);
    }
#undef A_ISSUE

#pragma unroll
    for (int mt = 0; mt < 2; mt++) {
        const float inv0 = 1.f / lrow[mt][0];
        const float inv1 = 1.f / lrow[mt][1];
        const int row = q0 + w * 32 + mt * 16 + g;
#pragma unroll
        for (int nt = 0; nt < 8; nt++) {
            const int dsti = h * HD_ + (nt >> 1) * 16 + 4 * tig + 2 * (nt & 1);
            *(__half2*)(O + (size_t)(b * S_ + row) * D_ + dsti) =
                __floats2half2_rn(o[mt][nt][0] * inv0, o[mt][nt][1] * inv0);
            *(__half2*)(O + (size_t)(b * S_ + row + 8) * D_ + dsti) =
                __floats2half2_rn(o[mt][nt][2] * inv1, o[mt][nt][3] * inv1);
        }
    }
}

// ---------------------------------------------------------------------------
// Launch
// ---------------------------------------------------------------------------
extern "C" void kernel_launch(void* const* d_in, const int* in_sizes, int n_in,
                              void* d_out, int out_size)
{
    const float* x  = (const float*)d_in[0];
    const float* Wq = (const float*)d_in[1];
    const float* Wk = (const float*)d_in[2];
    const float* Wv = (const float*)d_in[3];
    const float* bq = (const float*)d_in[4];
    const float* bk = (const float*)d_in[5];
    const float* bv = (const float*)d_in[6];
    const float* Wo = (const float*)d_in[7];
    const float* bo = (const float*)d_in[8];
    float* out = (float*)d_out;

    __half *xh, *qh, *kh, *vt, *ch, *wqh, *wkh, *wvh, *woh;
    cudaGetSymbolAddress((void**)&xh,  g_xh);
    cudaGetSymbolAddress((void**)&qh,  g_qh);
    cudaGetSymbolAddress((void**)&kh,  g_kh);
    cudaGetSymbolAddress((void**)&vt,  g_vt);
    cudaGetSymbolAddress((void**)&ch,  g_ch);
    cudaGetSymbolAddress((void**)&wqh, g_wq);
    cudaGetSymbolAddress((void**)&wkh, g_wk);
    cudaGetSymbolAddress((void**)&wvh, g_wv);
    cudaGetSymbolAddress((void**)&woh, g_wo);

    cudaFuncSetAttribute(gemm_h,
                         cudaFuncAttributeMaxDynamicSharedMemorySize, GEMM_SMEM);
    cudaFuncSetAttribute(attn_h,
                         cudaFuncAttributeMaxDynamicSharedMemorySize, ATTN_SMEM);

    const int n4all = N4X + 4 * N4W;
    prep_all<<<n4all / 256, 256>>>(x, Wq, Wk, Wv, Wo);

    // fused QKV: z=0 -> q (scale 0.125), z=1 -> k, z=2 -> Vt (key-permuted)
    gemm_h<<<dim3(D_ / GBN, M_TOTAL / GBM, 3), 256, GEMM_SMEM>>>(
        xh, wqh, wkh, wvh, bq, bk, bv, qh, kh, vt, 0);

    attn_h<<<dim3(S_ / 128, H_, B_), 128, ATTN_SMEM>>>(qh, kh, vt, ch);

    // output projection: fp32 plain out
    gemm_h<<<dim3(D_ / GBN, M_TOTAL / GBM, 1), 256, GEMM_SMEM>>>(
        ch, woh, woh, woh, bo, bo, bo, out, out, out, 1);
}

// round 10
// speedup vs baseline: 2.0056x; 1.0679x over previous
#include <cuda_runtime.h>
#include <cuda_fp16.h>
#include <cstdint>
#include <math.h>

// ---------------------------------------------------------------------------
// MultiHeadAttention: B=8, S=1024, D=1024, H=16, HD=64
// Round 9: GEMM BK 32->64 at same smem stride (80 halves): half the barriers,
// 2x MMAs per barrier interval, same buffers / occupancy (2 CTAs/SM).
// Attention and prep unchanged (round 7/8 winners).
// ---------------------------------------------------------------------------

#define B_  8
#define S_  1024
#define D_  1024
#define H_  16
#define HD_ 64
#define M_TOTAL (B_ * S_)          // 8192

__device__ __half g_xh[(size_t)M_TOTAL * D_];
__device__ __half g_qh[(size_t)M_TOTAL * D_];
__device__ __half g_kh[(size_t)M_TOTAL * D_];
__device__ __half g_vt[(size_t)B_ * H_ * HD_ * S_];   // [B][H][d][key-perm]
__device__ __half g_ch[(size_t)M_TOTAL * D_];
__device__ __half g_wq[(size_t)D_ * D_];
__device__ __half g_wk[(size_t)D_ * D_];
__device__ __half g_wv[(size_t)D_ * D_];
__device__ __half g_wo[(size_t)D_ * D_];

// ---------------------------------------------------------------------------
// helpers
// ---------------------------------------------------------------------------
__device__ __forceinline__ uint32_t smem_u32(const void* p) {
    uint32_t a;
    asm("{ .reg .u64 t; cvta.to.shared.u64 t, %1; cvt.u32.u64 %0, t; }"
        : "=r"(a) : "l"(p));
    return a;
}

__device__ __forceinline__ void cpa16(uint32_t dst, const void* src) {
    asm volatile("cp.async.cg.shared.global [%0], [%1], 16;"
                 :: "r"(dst), "l"(src) : "memory");
}
__device__ __forceinline__ void cpa_commit() {
    asm volatile("cp.async.commit_group;" ::: "memory");
}
__device__ __forceinline__ void cpa_wait1() {
    asm volatile("cp.async.wait_group 1;" ::: "memory");
}
__device__ __forceinline__ void cpa_wait0() {
    asm volatile("cp.async.wait_group 0;" ::: "memory");
}

__device__ __forceinline__ void mma_f16(float* c,
                                        uint32_t a0, uint32_t a1, uint32_t a2, uint32_t a3,
                                        uint32_t b0, uint32_t b1) {
    asm volatile(
        "mma.sync.aligned.m16n8k16.row.col.f32.f16.f16.f32 "
        "{%0,%1,%2,%3}, {%4,%5,%6,%7}, {%8,%9}, {%0,%1,%2,%3};\n"
        : "+f"(c[0]), "+f"(c[1]), "+f"(c[2]), "+f"(c[3])
        : "r"(a0), "r"(a1), "r"(a2), "r"(a3), "r"(b0), "r"(b1));
}

__device__ __forceinline__ uint32_t pack2(float lo, float hi) {
    __half2 h = __floats2half2_rn(lo, hi);
    return *reinterpret_cast<uint32_t*>(&h);
}

// ---------------------------------------------------------------------------
// Fused pre-pass (unchanged)
// ---------------------------------------------------------------------------
#define N4X (M_TOTAL * D_ / 4)     // 2097152
#define N4W (D_ * D_ / 4)          // 262144

__global__ __launch_bounds__(256)
void prep_all(const float* __restrict__ x,
              const float* __restrict__ Wq, const float* __restrict__ Wk,
              const float* __restrict__ Wv, const float* __restrict__ Wo)
{
    const int i = blockIdx.x * blockDim.x + threadIdx.x;
    const float* src;
    __half* dst;
    int j;
    if (i < N4X)                  { src = x;  dst = g_xh; j = i; }
    else {
        const int r = i - N4X;
        const int w = r >> 18;
        j = r & (N4W - 1);
        if      (w == 0) { src = Wq; dst = g_wq; }
        else if (w == 1) { src = Wk; dst = g_wk; }
        else if (w == 2) { src = Wv; dst = g_wv; }
        else             { src = Wo; dst = g_wo; }
    }
    const float4 v = ((const float4*)src)[j];
    const int flat = j << 2;
    const int base = flat & ~15;
    const int u0   = (flat & 15) >> 1;
    const int p0   = ((u0 & 3) << 1) | (u0 >> 2);
    const int u1   = u0 + 1;
    const int p1   = ((u1 & 3) << 1) | (u1 >> 2);
    *(__half2*)(dst + base + 2 * p0) = __floats2half2_rn(v.x, v.y);
    *(__half2*)(dst + base + 2 * p1) = __floats2half2_rn(v.z, v.w);
}

// ---------------------------------------------------------------------------
// fp16 GEMM (NT): CTA 128x128, BK=64, 8 warps of 32x64, 2-buffer cp.async,
// 2 CTAs/SM. Stride stays 80 halves (64 data + 16 pad): banks 8g+2tig,
// conflict-free. 16 iterations -> half the barriers of round 8.
// ---------------------------------------------------------------------------
#define GBM 128
#define GBN 128
#define GBKH 64
#define GLDH 80
#define GBUFH ((GBM + GBN) * GLDH)               // 20480 halves / buffer
#define GEMM_SMEM (2 * GBUFH * 2)                // 81920 bytes

__global__ __launch_bounds__(256, 2)
void gemm_h(const __half* __restrict__ A,
            const __half* __restrict__ W0, const __half* __restrict__ W1,
            const __half* __restrict__ W2,
            const float* __restrict__ bb0, const float* __restrict__ bb1,
            const float* __restrict__ bb2,
            void* C0, void* C1, void* C2,
            int oproj)
{
    extern __shared__ __half smh[];
    const int z = blockIdx.z;
    const __half* Bw   = (z == 0) ? W0  : (z == 1) ? W1  : W2;
    const float*  bias = (z == 0) ? bb0 : (z == 1) ? bb1 : bb2;
    void*         C    = (z == 0) ? C0  : (z == 1) ? C1  : C2;
    const float scale  = (!oproj && z == 0) ? 0.125f : 1.0f;

    const int tid  = threadIdx.x;
    const int wid  = tid >> 5;
    const int lane = tid & 31;
    const int g    = lane >> 2;
    const int tig  = lane & 3;
    const int wm   = (wid & 3) * 32;
    const int wn   = (wid >> 2) * 64;
    const int bm   = blockIdx.y * GBM;
    const int bn   = blockIdx.x * GBN;

    const __half* Abase = A  + (size_t)bm * D_;
    const __half* Bbase = Bw + (size_t)bn * D_;
    const uint32_t su   = smem_u32(smh);

    // stage one BK=64 slab (A: 128x64, B: 128x64) into buffer `buf`
#define G_ISSUE(slab, buf) do {                                            \
        const uint32_t s0 = su + (uint32_t)(buf) * (GBUFH * 2);            \
        const int k0 = (slab) * GBKH;                                      \
        _Pragma("unroll")                                                  \
        for (int j = 0; j < 4; j++) {                                      \
            const int i = tid + 256 * j;      /* A: 1024 16B chunks */     \
            const int row = i >> 3, ch = (i & 7) * 8;                      \
            cpa16(s0 + (row * GLDH + ch) * 2,                              \
                  Abase + (size_t)row * D_ + k0 + ch);                     \
        }                                                                  \
        _Pragma("unroll")                                                  \
        for (int j = 0; j < 4; j++) {                                      \
            const int i = tid + 256 * j;      /* B: 1024 16B chunks */     \
            const int row = i >> 3, ch = (i & 7) * 8;                      \
            cpa16(s0 + ((GBM + row) * GLDH + ch) * 2,                      \
                  Bbase + (size_t)row * D_ + k0 + ch);                     \
        }                                                                  \
        cpa_commit();                                                      \
    } while (0)

    float acc[2][8][4];
#pragma unroll
    for (int mt = 0; mt < 2; mt++)
#pragma unroll
        for (int nt = 0; nt < 8; nt++)
#pragma unroll
            for (int i = 0; i < 4; i++) acc[mt][nt][i] = 0.f;

    const int NT = D_ / GBKH;   // 16
    G_ISSUE(0, 0);
    G_ISSUE(1, 1);

    for (int t = 0; t < NT; t++) {
        if (t == NT - 1) cpa_wait0(); else cpa_wait1();
        __syncthreads();

        const __half* as = smh + (t & 1) * GBUFH;
        const __half* bs = as + GBM * GLDH;
#pragma unroll
        for (int ks = 0; ks < 4; ks++) {
            uint2 alo[2], ahi[2];
#pragma unroll
            for (int mt = 0; mt < 2; mt++) {
                const int r0 = (wm + mt * 16 + g) * GLDH + ks * 16 + 4 * tig;
                alo[mt] = *(const uint2*)&as[r0];
                ahi[mt] = *(const uint2*)&as[r0 + 8 * GLDH];
            }
#pragma unroll
            for (int nt = 0; nt < 8; nt++) {
                const uint2 bb = *(const uint2*)&bs[(wn + nt * 8 + g) * GLDH
                                                    + ks * 16 + 4 * tig];
#pragma unroll
                for (int mt = 0; mt < 2; mt++)
                    mma_f16(acc[mt][nt], alo[mt].x, ahi[mt].x, alo[mt].y, ahi[mt].y,
                            bb.x, bb.y);
            }
        }
        __syncthreads();                 // compute done before reissue
        if (t + 2 < NT) G_ISSUE(t + 2, t & 1);
    }
#undef G_ISSUE

    if (oproj) {
        float* Co = (float*)C;
#pragma unroll
        for (int mt = 0; mt < 2; mt++) {
            const int row0 = bm + wm + mt * 16 + g;
#pragma unroll
            for (int nt = 0; nt < 8; nt++) {
                const int col = bn + wn + nt * 8 + 2 * tig;
                const float c0 = bias[col], c1 = bias[col + 1];
                float2 v0 = make_float2(acc[mt][nt][0] + c0, acc[mt][nt][1] + c1);
                float2 v1 = make_float2(acc[mt][nt][2] + c0, acc[mt][nt][3] + c1);
                *(float2*)(Co + (size_t)row0 * D_ + col)       = v0;
                *(float2*)(Co + (size_t)(row0 + 8) * D_ + col) = v1;
            }
        }
    } else if (z < 2) {
        __half* Ch = (__half*)C;
#pragma unroll
        for (int mt = 0; mt < 2; mt++) {
            const int row0 = bm + wm + mt * 16 + g;
#pragma unroll
            for (int nt = 0; nt < 8; nt++) {
                const int n = bn + wn + nt * 8 + 2 * tig;
                const int dsti = bn + wn + (nt & ~1) * 8 + 4 * tig + 2 * (nt & 1);
                const float c0 = bias[n], c1 = bias[n + 1];
                *(__half2*)(Ch + (size_t)row0 * D_ + dsti) =
                    __floats2half2_rn((acc[mt][nt][0] + c0) * scale,
                                      (acc[mt][nt][1] + c1) * scale);
                *(__half2*)(Ch + (size_t)(row0 + 8) * D_ + dsti) =
                    __floats2half2_rn((acc[mt][nt][2] + c0) * scale,
                                      (acc[mt][nt][3] + c1) * scale);
            }
        }
    } else {
        // transposed Vt output with unit-permuted key positions
        __half* Vt = (__half*)C;
#pragma unroll
        for (int mt = 0; mt < 2; mt++) {
            const int row0 = bm + wm + mt * 16 + g;
#pragma unroll
            for (int nt = 0; nt < 8; nt++) {
                const int n  = bn + wn + nt * 8 + 2 * tig;
                const float c0 = bias[n], c1 = bias[n + 1];
#pragma unroll
                for (int e = 0; e < 4; e++) {
                    const int row = row0 + (e >> 1) * 8;
                    const int col = n + (e & 1);
                    const float val = acc[mt][nt][e] + ((e & 1) ? c1 : c0);
                    const int bIdx = row >> 10, s = row & 1023;
                    const int u    = (s >> 1) & 7;
                    const int sp   = (s & ~15) + 2 * (((u & 3) << 1) | (u >> 2)) + (s & 1);
                    const int head = col >> 6,  dd = col & 63;
                    Vt[(((size_t)(bIdx * H_ + head)) * HD_ + dd) * S_ + sp] =
                        __float2half_rn(val);
                }
            }
        }
    }
}

// ---------------------------------------------------------------------------
// Flash attention (unchanged): fp16 m16n8k16, cp.async double-buffered K/Vt,
// 2 CTAs/SM, Q frags hoisted, Vt key-permuted LDS.64 B-frags.
// ---------------------------------------------------------------------------
#define QLDH 80
#define KLDH 80
#define VLDH 80
#define OFF_K(buf) (128 * QLDH + (buf) * 64 * KLDH)
#define OFF_V(buf) (128 * QLDH + 2 * 64 * KLDH + (buf) * 64 * VLDH)
#define ATTN_SMEM ((128 * QLDH + 2 * 64 * KLDH + 2 * 64 * VLDH) * 2)  // 61440 B

__global__ __launch_bounds__(128, 2)
void attn_h(const __half* __restrict__ Q, const __half* __restrict__ K,
            const __half* __restrict__ Vt, __half* __restrict__ O)
{
    extern __shared__ __half smh[];
    const uint32_t su = smem_u32(smh);

    const int q0   = blockIdx.x * 128;
    const int h    = blockIdx.y;
    const int b    = blockIdx.z;
    const int tid  = threadIdx.x;
    const int w    = tid >> 5;
    const int lane = tid & 31;
    const int g    = lane >> 2;
    const int tig  = lane & 3;

    const size_t base  = (size_t)b * S_ * D_ + (size_t)h * HD_;
    const size_t vbase = ((size_t)(b * H_ + h)) * HD_ * S_;

#define A_ISSUE(t, buf) do {                                               \
        const __half* Kb = K  + base + (size_t)((t) * 64) * D_;            \
        const __half* Vb = Vt + vbase + (t) * 64;                          \
        _Pragma("unroll")                                                  \
        for (int j = 0; j < 4; j++) {                                      \
            const int i = tid + 128 * j;                                   \
            const int row = i >> 3, ch = (i & 7) * 8;                      \
            cpa16(su + (OFF_K(buf) + row * KLDH + ch) * 2,                 \
                  Kb + (size_t)row * D_ + ch);                             \
            cpa16(su + (OFF_V(buf) + row * VLDH + ch) * 2,                 \
                  Vb + (size_t)row * S_ + ch);                             \
        }                                                                  \
        cpa_commit();                                                      \
    } while (0)

    {
        const __half* Qb = Q + base + (size_t)q0 * D_;
#pragma unroll
        for (int j = 0; j < 8; j++) {
            const int i = tid + 128 * j;
            const int row = i >> 3, ch = (i & 7) * 8;
            cpa16(su + (row * QLDH + ch) * 2, Qb + (size_t)row * D_ + ch);
        }
        const __half* Kb = K + base;
        const __half* Vb = Vt + vbase;
#pragma unroll
        for (int j = 0; j < 4; j++) {
            const int i = tid + 128 * j;
            const int row = i >> 3, ch = (i & 7) * 8;
            cpa16(su + (OFF_K(0) + row * KLDH + ch) * 2, Kb + (size_t)row * D_ + ch);
            cpa16(su + (OFF_V(0) + row * VLDH + ch) * 2, Vb + (size_t)row * S_ + ch);
        }
        cpa_commit();
        A_ISSUE(1, 1);
    }

    float mrow[2][2], lrow[2][2];
#pragma unroll
    for (int mt = 0; mt < 2; mt++) {
        mrow[mt][0] = -1e30f; mrow[mt][1] = -1e30f;
        lrow[mt][0] = 0.f;    lrow[mt][1] = 0.f;
    }
    float o[2][8][4];
#pragma unroll
    for (int mt = 0; mt < 2; mt++)
#pragma unroll
        for (int nt = 0; nt < 8; nt++)
#pragma unroll
            for (int i = 0; i < 4; i++) o[mt][nt][i] = 0.f;

    uint2 qlo[2][4], qhi[2][4];

    const int NTILE = S_ / 64;   // 16
    for (int t = 0; t < NTILE; t++) {
        if (t == NTILE - 1) cpa_wait0(); else cpa_wait1();
        __syncthreads();

        if (t == 0) {
#pragma unroll
            for (int ks = 0; ks < 4; ks++)
#pragma unroll
                for (int mt = 0; mt < 2; mt++) {
                    const int r0 = (w * 32 + mt * 16 + g) * QLDH + ks * 16 + 4 * tig;
                    qlo[mt][ks] = *(const uint2*)&smh[r0];
                    qhi[mt][ks] = *(const uint2*)&smh[r0 + 8 * QLDH];
                }
        }

        const __half* sK = smh + OFF_K(t & 1);
        const __half* sV = smh + OFF_V(t & 1);

        float s[2][8][4];
#pragma unroll
        for (int mt = 0; mt < 2; mt++)
#pragma unroll
            for (int nt = 0; nt < 8; nt++)
#pragma unroll
                for (int i = 0; i < 4; i++) s[mt][nt][i] = 0.f;

#pragma unroll
        for (int ks = 0; ks < 4; ks++) {
#pragma unroll
            for (int nt = 0; nt < 8; nt++) {
                const uint2 bb = *(const uint2*)&sK[(nt * 8 + g) * KLDH
                                                    + ks * 16 + 4 * tig];
                mma_f16(s[0][nt], qlo[0][ks].x, qhi[0][ks].x, qlo[0][ks].y,
                        qhi[0][ks].y, bb.x, bb.y);
                mma_f16(s[1][nt], qlo[1][ks].x, qhi[1][ks].x, qlo[1][ks].y,
                        qhi[1][ks].y, bb.x, bb.y);
            }
        }

#pragma unroll
        for (int mt = 0; mt < 2; mt++) {
            float mx0 = -1e30f, mx1 = -1e30f;
#pragma unroll
            for (int nt = 0; nt < 8; nt++) {
                mx0 = fmaxf(mx0, fmaxf(s[mt][nt][0], s[mt][nt][1]));
                mx1 = fmaxf(mx1, fmaxf(s[mt][nt][2], s[mt][nt][3]));
            }
            mx0 = fmaxf(mx0, __shfl_xor_sync(0xffffffffu, mx0, 1));
            mx0 = fmaxf(mx0, __shfl_xor_sync(0xffffffffu, mx0, 2));
            mx1 = fmaxf(mx1, __shfl_xor_sync(0xffffffffu, mx1, 1));
            mx1 = fmaxf(mx1, __shfl_xor_sync(0xffffffffu, mx1, 2));

            const float nm0 = fmaxf(mrow[mt][0], mx0);
            const float nm1 = fmaxf(mrow[mt][1], mx1);
            const float al0 = __expf(mrow[mt][0] - nm0);
            const float al1 = __expf(mrow[mt][1] - nm1);
            mrow[mt][0] = nm0; mrow[mt][1] = nm1;

            float ps0 = 0.f, ps1 = 0.f;
#pragma unroll
            for (int nt = 0; nt < 8; nt++) {
                s[mt][nt][0] = __expf(s[mt][nt][0] - nm0);
                s[mt][nt][1] = __expf(s[mt][nt][1] - nm0);
                s[mt][nt][2] = __expf(s[mt][nt][2] - nm1);
                s[mt][nt][3] = __expf(s[mt][nt][3] - nm1);
                ps0 += s[mt][nt][0] + s[mt][nt][1];
                ps1 += s[mt][nt][2] + s[mt][nt][3];
            }
            ps0 += __shfl_xor_sync(0xffffffffu, ps0, 1);
            ps0 += __shfl_xor_sync(0xffffffffu, ps0, 2);
            ps1 += __shfl_xor_sync(0xffffffffu, ps1, 1);
            ps1 += __shfl_xor_sync(0xffffffffu, ps1, 2);
            lrow[mt][0] = lrow[mt][0] * al0 + ps0;
            lrow[mt][1] = lrow[mt][1] * al1 + ps1;

#pragma unroll
            for (int nt = 0; nt < 8; nt++) {
                o[mt][nt][0] *= al0; o[mt][nt][1] *= al0;
                o[mt][nt][2] *= al1; o[mt][nt][3] *= al1;
            }
        }

#pragma unroll
        for (int ks = 0; ks < 4; ks++) {
            uint32_t pa[2][4];
#pragma unroll
            for (int mt = 0; mt < 2; mt++) {
                pa[mt][0] = pack2(s[mt][2 * ks][0],     s[mt][2 * ks][1]);
                pa[mt][1] = pack2(s[mt][2 * ks][2],     s[mt][2 * ks][3]);
                pa[mt][2] = pack2(s[mt][2 * ks + 1][0], s[mt][2 * ks + 1][1]);
                pa[mt][3] = pack2(s[mt][2 * ks + 1][2], s[mt][2 * ks + 1][3]);
            }
#pragma unroll
            for (int nt = 0; nt < 8; nt++) {
                const uint2 bb = *(const uint2*)&sV[(nt * 8 + g) * VLDH
                                                    + ks * 16 + 4 * tig];
                mma_f16(o[0][nt], pa[0][0], pa[0][1], pa[0][2], pa[0][3], bb.x, bb.y);
                mma_f16(o[1][nt], pa[1][0], pa[1][1], pa[1][2], pa[1][3], bb.x, bb.y);
            }
        }

        __syncthreads();
        if (t + 2 < NTILE) A_ISSUE(t + 2, t & 1);
    }
#undef A_ISSUE

#pragma unroll
    for (int mt = 0; mt < 2; mt++) {
        const float inv0 = 1.f / lrow[mt][0];
        const float inv1 = 1.f / lrow[mt][1];
        const int row = q0 + w * 32 + mt * 16 + g;
#pragma unroll
        for (int nt = 0; nt < 8; nt++) {
            const int dsti = h * HD_ + (nt >> 1) * 16 + 4 * tig + 2 * (nt & 1);
            *(__half2*)(O + (size_t)(b * S_ + row) * D_ + dsti) =
                __floats2half2_rn(o[mt][nt][0] * inv0, o[mt][nt][1] * inv0);
            *(__half2*)(O + (size_t)(b * S_ + row + 8) * D_ + dsti) =
                __floats2half2_rn(o[mt][nt][2] * inv1, o[mt][nt][3] * inv1);
        }
    }
}

// ---------------------------------------------------------------------------
// Launch
// ---------------------------------------------------------------------------
extern "C" void kernel_launch(void* const* d_in, const int* in_sizes, int n_in,
                              void* d_out, int out_size)
{
    const float* x  = (const float*)d_in[0];
    const float* Wq = (const float*)d_in[1];
    const float* Wk = (const float*)d_in[2];
    const float* Wv = (const float*)d_in[3];
    const float* bq = (const float*)d_in[4];
    const float* bk = (const float*)d_in[5];
    const float* bv = (const float*)d_in[6];
    const float* Wo = (const float*)d_in[7];
    const float* bo = (const float*)d_in[8];
    float* out = (float*)d_out;

    __half *xh, *qh, *kh, *vt, *ch, *wqh, *wkh, *wvh, *woh;
    cudaGetSymbolAddress((void**)&xh,  g_xh);
    cudaGetSymbolAddress((void**)&qh,  g_qh);
    cudaGetSymbolAddress((void**)&kh,  g_kh);
    cudaGetSymbolAddress((void**)&vt,  g_vt);
    cudaGetSymbolAddress((void**)&ch,  g_ch);
    cudaGetSymbolAddress((void**)&wqh, g_wq);
    cudaGetSymbolAddress((void**)&wkh, g_wk);
    cudaGetSymbolAddress((void**)&wvh, g_wv);
    cudaGetSymbolAddress((void**)&woh, g_wo);

    cudaFuncSetAttribute(gemm_h,
                         cudaFuncAttributeMaxDynamicSharedMemorySize, GEMM_SMEM);
    cudaFuncSetAttribute(attn_h,
                         cudaFuncAttributeMaxDynamicSharedMemorySize, ATTN_SMEM);

    const int n4all = N4X + 4 * N4W;
    prep_all<<<n4all / 256, 256>>>(x, Wq, Wk, Wv, Wo);

    // fused QKV: z=0 -> q (scale 0.125), z=1 -> k, z=2 -> Vt (key-permuted)
    gemm_h<<<dim3(D_ / GBN, M_TOTAL / GBM, 3), 256, GEMM_SMEM>>>(
        xh, wqh, wkh, wvh, bq, bk, bv, qh, kh, vt, 0);

    attn_h<<<dim3(S_ / 128, H_, B_), 128, ATTN_SMEM>>>(qh, kh, vt, ch);

    // output projection: fp32 plain out
    gemm_h<<<dim3(D_ / GBN, M_TOTAL / GBM, 1), 256, GEMM_SMEM>>>(
        ch, woh, woh, woh, bo, bo, bo, out, out, out, 1);
}

// round 11
// speedup vs baseline: 2.0181x; 1.0062x over previous
#include <cuda_runtime.h>
#include <cuda_fp16.h>
#include <cstdint>
#include <math.h>

// ---------------------------------------------------------------------------
// MultiHeadAttention: B=8, S=1024, D=1024, H=16, HD=64
// Round 10: GEMM retiled to the attention-validated shape: 128-thread CTAs,
// 4 warps of 64x64 (acc=128 regs, <=255 reg budget), BK=64, 2 CTAs/SM.
// 2x MMAs per warp per barrier interval vs round 9.
// Attention and prep unchanged.
// ---------------------------------------------------------------------------

#define B_  8
#define S_  1024
#define D_  1024
#define H_  16
#define HD_ 64
#define M_TOTAL (B_ * S_)          // 8192

__device__ __half g_xh[(size_t)M_TOTAL * D_];
__device__ __half g_qh[(size_t)M_TOTAL * D_];
__device__ __half g_kh[(size_t)M_TOTAL * D_];
__device__ __half g_vt[(size_t)B_ * H_ * HD_ * S_];   // [B][H][d][key-perm]
__device__ __half g_ch[(size_t)M_TOTAL * D_];
__device__ __half g_wq[(size_t)D_ * D_];
__device__ __half g_wk[(size_t)D_ * D_];
__device__ __half g_wv[(size_t)D_ * D_];
__device__ __half g_wo[(size_t)D_ * D_];

// ---------------------------------------------------------------------------
// helpers
// ---------------------------------------------------------------------------
__device__ __forceinline__ uint32_t smem_u32(const void* p) {
    uint32_t a;
    asm("{ .reg .u64 t; cvta.to.shared.u64 t, %1; cvt.u32.u64 %0, t; }"
        : "=r"(a) : "l"(p));
    return a;
}

__device__ __forceinline__ void cpa16(uint32_t dst, const void* src) {
    asm volatile("cp.async.cg.shared.global [%0], [%1], 16;"
                 :: "r"(dst), "l"(src) : "memory");
}
__device__ __forceinline__ void cpa_commit() {
    asm volatile("cp.async.commit_group;" ::: "memory");
}
__device__ __forceinline__ void cpa_wait1() {
    asm volatile("cp.async.wait_group 1;" ::: "memory");
}
__device__ __forceinline__ void cpa_wait0() {
    asm volatile("cp.async.wait_group 0;" ::: "memory");
}

__device__ __forceinline__ void mma_f16(float* c,
                                        uint32_t a0, uint32_t a1, uint32_t a2, uint32_t a3,
                                        uint32_t b0, uint32_t b1) {
    asm volatile(
        "mma.sync.aligned.m16n8k16.row.col.f32.f16.f16.f32 "
        "{%0,%1,%2,%3}, {%4,%5,%6,%7}, {%8,%9}, {%0,%1,%2,%3};\n"
        : "+f"(c[0]), "+f"(c[1]), "+f"(c[2]), "+f"(c[3])
        : "r"(a0), "r"(a1), "r"(a2), "r"(a3), "r"(b0), "r"(b1));
}

__device__ __forceinline__ uint32_t pack2(float lo, float hi) {
    __half2 h = __floats2half2_rn(lo, hi);
    return *reinterpret_cast<uint32_t*>(&h);
}

// ---------------------------------------------------------------------------
// Fused pre-pass (unchanged)
// ---------------------------------------------------------------------------
#define N4X (M_TOTAL * D_ / 4)     // 2097152
#define N4W (D_ * D_ / 4)          // 262144

__global__ __launch_bounds__(256)
void prep_all(const float* __restrict__ x,
              const float* __restrict__ Wq, const float* __restrict__ Wk,
              const float* __restrict__ Wv, const float* __restrict__ Wo)
{
    const int i = blockIdx.x * blockDim.x + threadIdx.x;
    const float* src;
    __half* dst;
    int j;
    if (i < N4X)                  { src = x;  dst = g_xh; j = i; }
    else {
        const int r = i - N4X;
        const int w = r >> 18;
        j = r & (N4W - 1);
        if      (w == 0) { src = Wq; dst = g_wq; }
        else if (w == 1) { src = Wk; dst = g_wk; }
        else if (w == 2) { src = Wv; dst = g_wv; }
        else             { src = Wo; dst = g_wo; }
    }
    const float4 v = ((const float4*)src)[j];
    const int flat = j << 2;
    const int base = flat & ~15;
    const int u0   = (flat & 15) >> 1;
    const int p0   = ((u0 & 3) << 1) | (u0 >> 2);
    const int u1   = u0 + 1;
    const int p1   = ((u1 & 3) << 1) | (u1 >> 2);
    *(__half2*)(dst + base + 2 * p0) = __floats2half2_rn(v.x, v.y);
    *(__half2*)(dst + base + 2 * p1) = __floats2half2_rn(v.z, v.w);
}

// ---------------------------------------------------------------------------
// fp16 GEMM (NT): CTA 128x128 with 128 threads (4 warps of 64x64), BK=64,
// 2-buffer cp.async, 2 CTAs/SM (reg budget 256/thread). Stride 80 halves,
// conflict-free. 128 MMAs per warp per barrier interval.
// ---------------------------------------------------------------------------
#define GBM 128
#define GBN 128
#define GBKH 64
#define GLDH 80
#define GBUFH ((GBM + GBN) * GLDH)               // 20480 halves / buffer
#define GEMM_SMEM (2 * GBUFH * 2)                // 81920 bytes

__global__ __launch_bounds__(128, 2)
void gemm_h(const __half* __restrict__ A,
            const __half* __restrict__ W0, const __half* __restrict__ W1,
            const __half* __restrict__ W2,
            const float* __restrict__ bb0, const float* __restrict__ bb1,
            const float* __restrict__ bb2,
            void* C0, void* C1, void* C2,
            int oproj)
{
    extern __shared__ __half smh[];
    const int z = blockIdx.z;
    const __half* Bw   = (z == 0) ? W0  : (z == 1) ? W1  : W2;
    const float*  bias = (z == 0) ? bb0 : (z == 1) ? bb1 : bb2;
    void*         C    = (z == 0) ? C0  : (z == 1) ? C1  : C2;
    const float scale  = (!oproj && z == 0) ? 0.125f : 1.0f;

    const int tid  = threadIdx.x;
    const int wid  = tid >> 5;
    const int lane = tid & 31;
    const int g    = lane >> 2;
    const int tig  = lane & 3;
    const int wm   = (wid & 1) * 64;     // 2x2 warps over 128x128
    const int wn   = (wid >> 1) * 64;
    const int bm   = blockIdx.y * GBM;
    const int bn   = blockIdx.x * GBN;

    const __half* Abase = A  + (size_t)bm * D_;
    const __half* Bbase = Bw + (size_t)bn * D_;
    const uint32_t su   = smem_u32(smh);

    // stage one BK=64 slab (A: 128x64, B: 128x64) with 128 threads
#define G_ISSUE(slab, buf) do {                                            \
        const uint32_t s0 = su + (uint32_t)(buf) * (GBUFH * 2);            \
        const int k0 = (slab) * GBKH;                                      \
        _Pragma("unroll")                                                  \
        for (int j = 0; j < 8; j++) {                                      \
            const int i = tid + 128 * j;      /* A: 1024 16B chunks */     \
            const int row = i >> 3, ch = (i & 7) * 8;                      \
            cpa16(s0 + (row * GLDH + ch) * 2,                              \
                  Abase + (size_t)row * D_ + k0 + ch);                     \
        }                                                                  \
        _Pragma("unroll")                                                  \
        for (int j = 0; j < 8; j++) {                                      \
            const int i = tid + 128 * j;      /* B: 1024 16B chunks */     \
            const int row = i >> 3, ch = (i & 7) * 8;                      \
            cpa16(s0 + ((GBM + row) * GLDH + ch) * 2,                      \
                  Bbase + (size_t)row * D_ + k0 + ch);                     \
        }                                                                  \
        cpa_commit();                                                      \
    } while (0)

    float acc[4][8][4];
#pragma unroll
    for (int mt = 0; mt < 4; mt++)
#pragma unroll
        for (int nt = 0; nt < 8; nt++)
#pragma unroll
            for (int i = 0; i < 4; i++) acc[mt][nt][i] = 0.f;

    const int NT = D_ / GBKH;   // 16
    G_ISSUE(0, 0);
    G_ISSUE(1, 1);

    for (int t = 0; t < NT; t++) {
        if (t == NT - 1) cpa_wait0(); else cpa_wait1();
        __syncthreads();

        const __half* as = smh + (t & 1) * GBUFH;
        const __half* bs = as + GBM * GLDH;
#pragma unroll
        for (int ks = 0; ks < 4; ks++) {
            uint2 alo[4], ahi[4];
#pragma unroll
            for (int mt = 0; mt < 4; mt++) {
                const int r0 = (wm + mt * 16 + g) * GLDH + ks * 16 + 4 * tig;
                alo[mt] = *(const uint2*)&as[r0];
                ahi[mt] = *(const uint2*)&as[r0 + 8 * GLDH];
            }
#pragma unroll
            for (int nt = 0; nt < 8; nt++) {
                const uint2 bb = *(const uint2*)&bs[(wn + nt * 8 + g) * GLDH
                                                    + ks * 16 + 4 * tig];
#pragma unroll
                for (int mt = 0; mt < 4; mt++)
                    mma_f16(acc[mt][nt], alo[mt].x, ahi[mt].x, alo[mt].y, ahi[mt].y,
                            bb.x, bb.y);
            }
        }
        __syncthreads();                 // compute done before reissue
        if (t + 2 < NT) G_ISSUE(t + 2, t & 1);
    }
#undef G_ISSUE

    if (oproj) {
        float* Co = (float*)C;
#pragma unroll
        for (int mt = 0; mt < 4; mt++) {
            const int row0 = bm + wm + mt * 16 + g;
#pragma unroll
            for (int nt = 0; nt < 8; nt++) {
                const int col = bn + wn + nt * 8 + 2 * tig;
                const float c0 = bias[col], c1 = bias[col + 1];
                float2 v0 = make_float2(acc[mt][nt][0] + c0, acc[mt][nt][1] + c1);
                float2 v1 = make_float2(acc[mt][nt][2] + c0, acc[mt][nt][3] + c1);
                *(float2*)(Co + (size_t)row0 * D_ + col)       = v0;
                *(float2*)(Co + (size_t)(row0 + 8) * D_ + col) = v1;
            }
        }
    } else if (z < 2) {
        __half* Ch = (__half*)C;
#pragma unroll
        for (int mt = 0; mt < 4; mt++) {
            const int row0 = bm + wm + mt * 16 + g;
#pragma unroll
            for (int nt = 0; nt < 8; nt++) {
                const int n = bn + wn + nt * 8 + 2 * tig;
                const int dsti = bn + wn + (nt & ~1) * 8 + 4 * tig + 2 * (nt & 1);
                const float c0 = bias[n], c1 = bias[n + 1];
                *(__half2*)(Ch + (size_t)row0 * D_ + dsti) =
                    __floats2half2_rn((acc[mt][nt][0] + c0) * scale,
                                      (acc[mt][nt][1] + c1) * scale);
                *(__half2*)(Ch + (size_t)(row0 + 8) * D_ + dsti) =
                    __floats2half2_rn((acc[mt][nt][2] + c0) * scale,
                                      (acc[mt][nt][3] + c1) * scale);
            }
        }
    } else {
        // transposed Vt output with unit-permuted key positions
        __half* Vt = (__half*)C;
#pragma unroll
        for (int mt = 0; mt < 4; mt++) {
            const int row0 = bm + wm + mt * 16 + g;
#pragma unroll
            for (int nt = 0; nt < 8; nt++) {
                const int n  = bn + wn + nt * 8 + 2 * tig;
                const float c0 = bias[n], c1 = bias[n + 1];
#pragma unroll
                for (int e = 0; e < 4; e++) {
                    const int row = row0 + (e >> 1) * 8;
                    const int col = n + (e & 1);
                    const float val = acc[mt][nt][e] + ((e & 1) ? c1 : c0);
                    const int bIdx = row >> 10, s = row & 1023;
                    const int u    = (s >> 1) & 7;
                    const int sp   = (s & ~15) + 2 * (((u & 3) << 1) | (u >> 2)) + (s & 1);
                    const int head = col >> 6,  dd = col & 63;
                    Vt[(((size_t)(bIdx * H_ + head)) * HD_ + dd) * S_ + sp] =
                        __float2half_rn(val);
                }
            }
        }
    }
}

// ---------------------------------------------------------------------------
// Flash attention (unchanged): fp16 m16n8k16, cp.async double-buffered K/Vt,
// 2 CTAs/SM, Q frags hoisted, Vt key-permuted LDS.64 B-frags.
// ---------------------------------------------------------------------------
#define QLDH 80
#define KLDH 80
#define VLDH 80
#define OFF_K(buf) (128 * QLDH + (buf) * 64 * KLDH)
#define OFF_V(buf) (128 * QLDH + 2 * 64 * KLDH + (buf) * 64 * VLDH)
#define ATTN_SMEM ((128 * QLDH + 2 * 64 * KLDH + 2 * 64 * VLDH) * 2)  // 61440 B

__global__ __launch_bounds__(128, 2)
void attn_h(const __half* __restrict__ Q, const __half* __restrict__ K,
            const __half* __restrict__ Vt, __half* __restrict__ O)
{
    extern __shared__ __half smh[];
    const uint32_t su = smem_u32(smh);

    const int q0   = blockIdx.x * 128;
    const int h    = blockIdx.y;
    const int b    = blockIdx.z;
    const int tid  = threadIdx.x;
    const int w    = tid >> 5;
    const int lane = tid & 31;
    const int g    = lane >> 2;
    const int tig  = lane & 3;

    const size_t base  = (size_t)b * S_ * D_ + (size_t)h * HD_;
    const size_t vbase = ((size_t)(b * H_ + h)) * HD_ * S_;

#define A_ISSUE(t, buf) do {                                               \
        const __half* Kb = K  + base + (size_t)((t) * 64) * D_;            \
        const __half* Vb = Vt + vbase + (t) * 64;                          \
        _Pragma("unroll")                                                  \
        for (int j = 0; j < 4; j++) {                                      \
            const int i = tid + 128 * j;                                   \
            const int row = i >> 3, ch = (i & 7) * 8;                      \
            cpa16(su + (OFF_K(buf) + row * KLDH + ch) * 2,                 \
                  Kb + (size_t)row * D_ + ch);                             \
            cpa16(su + (OFF_V(buf) + row * VLDH + ch) * 2,                 \
                  Vb + (size_t)row * S_ + ch);                             \
        }                                                                  \
        cpa_commit();                                                      \
    } while (0)

    {
        const __half* Qb = Q + base + (size_t)q0 * D_;
#pragma unroll
        for (int j = 0; j < 8; j++) {
            const int i = tid + 128 * j;
            const int row = i >> 3, ch = (i & 7) * 8;
            cpa16(su + (row * QLDH + ch) * 2, Qb + (size_t)row * D_ + ch);
        }
        const __half* Kb = K + base;
        const __half* Vb = Vt + vbase;
#pragma unroll
        for (int j = 0; j < 4; j++) {
            const int i = tid + 128 * j;
            const int row = i >> 3, ch = (i & 7) * 8;
            cpa16(su + (OFF_K(0) + row * KLDH + ch) * 2, Kb + (size_t)row * D_ + ch);
            cpa16(su + (OFF_V(0) + row * VLDH + ch) * 2, Vb + (size_t)row * S_ + ch);
        }
        cpa_commit();
        A_ISSUE(1, 1);
    }

    float mrow[2][2], lrow[2][2];
#pragma unroll
    for (int mt = 0; mt < 2; mt++) {
        mrow[mt][0] = -1e30f; mrow[mt][1] = -1e30f;
        lrow[mt][0] = 0.f;    lrow[mt][1] = 0.f;
    }
    float o[2][8][4];
#pragma unroll
    for (int mt = 0; mt < 2; mt++)
#pragma unroll
        for (int nt = 0; nt < 8; nt++)
#pragma unroll
            for (int i = 0; i < 4; i++) o[mt][nt][i] = 0.f;

    uint2 qlo[2][4], qhi[2][4];

    const int NTILE = S_ / 64;   // 16
    for (int t = 0; t < NTILE; t++) {
        if (t == NTILE - 1) cpa_wait0(); else cpa_wait1();
        __syncthreads();

        if (t == 0) {
#pragma unroll
            for (int ks = 0; ks < 4; ks++)
#pragma unroll
                for (int mt = 0; mt < 2; mt++) {
                    const int r0 = (w * 32 + mt * 16 + g) * QLDH + ks * 16 + 4 * tig;
                    qlo[mt][ks] = *(const uint2*)&smh[r0];
                    qhi[mt][ks] = *(const uint2*)&smh[r0 + 8 * QLDH];
                }
        }

        const __half* sK = smh + OFF_K(t & 1);
        const __half* sV = smh + OFF_V(t & 1);

        float s[2][8][4];
#pragma unroll
        for (int mt = 0; mt < 2; mt++)
#pragma unroll
            for (int nt = 0; nt < 8; nt++)
#pragma unroll
                for (int i = 0; i < 4; i++) s[mt][nt][i] = 0.f;

#pragma unroll
        for (int ks = 0; ks < 4; ks++) {
#pragma unroll
            for (int nt = 0; nt < 8; nt++) {
                const uint2 bb = *(const uint2*)&sK[(nt * 8 + g) * KLDH
                                                    + ks * 16 + 4 * tig];
                mma_f16(s[0][nt], qlo[0][ks].x, qhi[0][ks].x, qlo[0][ks].y,
                        qhi[0][ks].y, bb.x, bb.y);
                mma_f16(s[1][nt], qlo[1][ks].x, qhi[1][ks].x, qlo[1][ks].y,
                        qhi[1][ks].y, bb.x, bb.y);
            }
        }

#pragma unroll
        for (int mt = 0; mt < 2; mt++) {
            float mx0 = -1e30f, mx1 = -1e30f;
#pragma unroll
            for (int nt = 0; nt < 8; nt++) {
                mx0 = fmaxf(mx0, fmaxf(s[mt][nt][0], s[mt][nt][1]));
                mx1 = fmaxf(mx1, fmaxf(s[mt][nt][2], s[mt][nt][3]));
            }
            mx0 = fmaxf(mx0, __shfl_xor_sync(0xffffffffu, mx0, 1));
            mx0 = fmaxf(mx0, __shfl_xor_sync(0xffffffffu, mx0, 2));
            mx1 = fmaxf(mx1, __shfl_xor_sync(0xffffffffu, mx1, 1));
            mx1 = fmaxf(mx1, __shfl_xor_sync(0xffffffffu, mx1, 2));

            const float nm0 = fmaxf(mrow[mt][0], mx0);
            const float nm1 = fmaxf(mrow[mt][1], mx1);
            const float al0 = __expf(mrow[mt][0] - nm0);
            const float al1 = __expf(mrow[mt][1] - nm1);
            mrow[mt][0] = nm0; mrow[mt][1] = nm1;

            float ps0 = 0.f, ps1 = 0.f;
#pragma unroll
            for (int nt = 0; nt < 8; nt++) {
                s[mt][nt][0] = __expf(s[mt][nt][0] - nm0);
                s[mt][nt][1] = __expf(s[mt][nt][1] - nm0);
                s[mt][nt][2] = __expf(s[mt][nt][2] - nm1);
                s[mt][nt][3] = __expf(s[mt][nt][3] - nm1);
                ps0 += s[mt][nt][0] + s[mt][nt][1];
                ps1 += s[mt][nt][2] + s[mt][nt][3];
            }
            ps0 += __shfl_xor_sync(0xffffffffu, ps0, 1);
            ps0 += __shfl_xor_sync(0xffffffffu, ps0, 2);
            ps1 += __shfl_xor_sync(0xffffffffu, ps1, 1);
            ps1 += __shfl_xor_sync(0xffffffffu, ps1, 2);
            lrow[mt][0] = lrow[mt][0] * al0 + ps0;
            lrow[mt][1] = lrow[mt][1] * al1 + ps1;

#pragma unroll
            for (int nt = 0; nt < 8; nt++) {
                o[mt][nt][0] *= al0; o[mt][nt][1] *= al0;
                o[mt][nt][2] *= al1; o[mt][nt][3] *= al1;
            }
        }

#pragma unroll
        for (int ks = 0; ks < 4; ks++) {
            uint32_t pa[2][4];
#pragma unroll
            for (int mt = 0; mt < 2; mt++) {
                pa[mt][0] = pack2(s[mt][2 * ks][0],     s[mt][2 * ks][1]);
                pa[mt][1] = pack2(s[mt][2 * ks][2],     s[mt][2 * ks][3]);
                pa[mt][2] = pack2(s[mt][2 * ks + 1][0], s[mt][2 * ks + 1][1]);
                pa[mt][3] = pack2(s[mt][2 * ks + 1][2], s[mt][2 * ks + 1][3]);
            }
#pragma unroll
            for (int nt = 0; nt < 8; nt++) {
                const uint2 bb = *(const uint2*)&sV[(nt * 8 + g) * VLDH
                                                    + ks * 16 + 4 * tig];
                mma_f16(o[0][nt], pa[0][0], pa[0][1], pa[0][2], pa[0][3], bb.x, bb.y);
                mma_f16(o[1][nt], pa[1][0], pa[1][1], pa[1][2], pa[1][3], bb.x, bb.y);
            }
        }

        __syncthreads();
        if (t + 2 < NTILE) A_ISSUE(t + 2, t & 1);
    }
#undef A_ISSUE

#pragma unroll
    for (int mt = 0; mt < 2; mt++) {
        const float inv0 = 1.f / lrow[mt][0];
        const float inv1 = 1.f / lrow[mt][1];
        const int row = q0 + w * 32 + mt * 16 + g;
#pragma unroll
        for (int nt = 0; nt < 8; nt++) {
            const int dsti = h * HD_ + (nt >> 1) * 16 + 4 * tig + 2 * (nt & 1);
            *(__half2*)(O + (size_t)(b * S_ + row) * D_ + dsti) =
                __floats2half2_rn(o[mt][nt][0] * inv0, o[mt][nt][1] * inv0);
            *(__half2*)(O + (size_t)(b * S_ + row + 8) * D_ + dsti) =
                __floats2half2_rn(o[mt][nt][2] * inv1, o[mt][nt][3] * inv1);
        }
    }
}

// ---------------------------------------------------------------------------
// Launch
// ---------------------------------------------------------------------------
extern "C" void kernel_launch(void* const* d_in, const int* in_sizes, int n_in,
                              void* d_out, int out_size)
{
    const float* x  = (const float*)d_in[0];
    const float* Wq = (const float*)d_in[1];
    const float* Wk = (const float*)d_in[2];
    const float* Wv = (const float*)d_in[3];
    const float* bq = (const float*)d_in[4];
    const float* bk = (const float*)d_in[5];
    const float* bv = (const float*)d_in[6];
    const float* Wo = (const float*)d_in[7];
    const float* bo = (const float*)d_in[8];
    float* out = (float*)d_out;

    __half *xh, *qh, *kh, *vt, *ch, *wqh, *wkh, *wvh, *woh;
    cudaGetSymbolAddress((void**)&xh,  g_xh);
    cudaGetSymbolAddress((void**)&qh,  g_qh);
    cudaGetSymbolAddress((void**)&kh,  g_kh);
    cudaGetSymbolAddress((void**)&vt,  g_vt);
    cudaGetSymbolAddress((void**)&ch,  g_ch);
    cudaGetSymbolAddress((void**)&wqh, g_wq);
    cudaGetSymbolAddress((void**)&wkh, g_wk);
    cudaGetSymbolAddress((void**)&wvh, g_wv);
    cudaGetSymbolAddress((void**)&woh, g_wo);

    cudaFuncSetAttribute(gemm_h,
                         cudaFuncAttributeMaxDynamicSharedMemorySize, GEMM_SMEM);
    cudaFuncSetAttribute(attn_h,
                         cudaFuncAttributeMaxDynamicSharedMemorySize, ATTN_SMEM);

    const int n4all = N4X + 4 * N4W;
    prep_all<<<n4all / 256, 256>>>(x, Wq, Wk, Wv, Wo);

    // fused QKV: z=0 -> q (scale 0.125), z=1 -> k, z=2 -> Vt (key-permuted)
    gemm_h<<<dim3(D_ / GBN, M_TOTAL / GBM, 3), 128, GEMM_SMEM>>>(
        xh, wqh, wkh, wvh, bq, bk, bv, qh, kh, vt, 0);

    attn_h<<<dim3(S_ / 128, H_, B_), 128, ATTN_SMEM>>>(qh, kh, vt, ch);

    // output projection: fp32 plain out
    gemm_h<<<dim3(D_ / GBN, M_TOTAL / GBM, 1), 128, GEMM_SMEM>>>(
        ch, woh, woh, woh, bo, bo, bo, out, out, out, 1);
}